// round 14
// baseline (speedup 1.0000x reference)
#include <cuda_runtime.h>
#include <cuda_fp16.h>
#include <mma.h>
#include <cstdint>

using namespace nvcuda;

// ---------------- problem constants ----------------
constexpr int B_  = 8;
constexpr int M_  = 8;
constexpr int D_  = 512;
constexpr int DH_ = 64;
constexpr int O_  = 64;
constexpr int SS_ = 72;    // M + O

constexpr int NTT = B_ * 512 * M_;  // 32768 temporal rows
constexpr int NSS = B_ * SS_;       // 576 ss rows
constexpr int NXR = NTT + NSS;      // 33344 gathered rows
constexpr int NXP = 33408;          // padded to 261*128

constexpr long long SZ_TOUT = (long long)B_ * 513 * M_ * D_;
constexpr long long SZ_OOUT = (long long)B_ * O_ * D_;
constexpr long long SZ_TATT = (long long)B_ * 8 * 512 * M_ * SS_;
constexpr long long OFF_OOUT = SZ_TOUT;
constexpr long long OFF_TATT = OFF_OOUT + SZ_OOUT;
constexpr long long OFF_OATT = OFF_TATT + SZ_TATT;

// ---------------- scratch ----------------
__device__ __half g_x[(size_t)NXP * D_];       // gathered fp16 inputs (rows >= NXR stay 0)
__device__ __half g_w[3][D_ * D_];             // fp16 weights
__device__ __half g_tt[3][(size_t)NTT * D_];   // Qtt, Ktt, Vtt (no bias)
__device__ __half g_ss[3][(size_t)NSS * D_];   // Qss, Kss, Vss (no bias)

// ============================================================================
// Prologue: fp32 -> fp16 convert + gather (X) and weight convert.
// ============================================================================
constexpr int NCHX = NXR * (D_ / 8);
constexpr int NCHW = 3 * D_ * (D_ / 8);
constexpr int NCONV = NCHX + NCHW;

__global__ __launch_bounds__(256) void convert_kernel(
    const float* __restrict__ Xt, const float* __restrict__ Xo,
    const float* __restrict__ Wq, const float* __restrict__ Wk,
    const float* __restrict__ Wv)
{
    int idx = blockIdx.x * 256 + threadIdx.x;
    if (idx >= NCONV) return;
    const float* src;
    __half* dst;
    if (idx < NCHX) {
        int r = idx >> 6;
        int c = (idx & 63) * 8;
        if (r < NTT) {
            src = Xt + (size_t)(r + ((r >> 12) << 3) + 8) * D_ + c;
        } else {
            int j = r - NTT;
            int bb = j / SS_;
            int jj = j - bb * SS_;
            src = ((jj < M_) ? (Xt + (size_t)(bb * 4104 + jj) * D_)
                             : (Xo + (size_t)(bb * O_ + jj - M_) * D_)) + c;
        }
        dst = g_x + (size_t)r * D_ + c;
    } else {
        int k = idx - NCHX;
        int mat = k / (D_ * 64);
        int rem = k - mat * (D_ * 64);
        int r = rem >> 6;
        int c = (rem & 63) * 8;
        const float* W = (mat == 0) ? Wq : ((mat == 1) ? Wk : Wv);
        src = W + (size_t)r * D_ + c;
        dst = g_w[mat] + (size_t)r * D_ + c;
    }
    float4 a = *reinterpret_cast<const float4*>(src);
    float4 b = *reinterpret_cast<const float4*>(src + 4);
    union { uint4 u; __half2 h[4]; } pk;
    pk.h[0] = __floats2half2_rn(a.x, a.y);
    pk.h[1] = __floats2half2_rn(a.z, a.w);
    pk.h[2] = __floats2half2_rn(b.x, b.y);
    pk.h[3] = __floats2half2_rn(b.z, b.w);
    *reinterpret_cast<uint4*>(dst) = pk.u;
}

// ---------------- cp.async helpers ----------------
__device__ __forceinline__ uint32_t smem_u32(const void* p) {
    uint32_t a;
    asm("{ .reg .u64 t; cvta.to.shared.u64 t, %1; cvt.u32.u64 %0, t; }" : "=r"(a) : "l"(p));
    return a;
}
__device__ __forceinline__ void cp16(uint32_t s, const void* g) {
    asm volatile("cp.async.cg.shared.global [%0], [%1], 16;" :: "r"(s), "l"(g) : "memory");
}
#define CP_COMMIT() asm volatile("cp.async.commit_group;" ::: "memory")
#define CP_WAIT1()  asm volatile("cp.async.wait_group 1;" ::: "memory")
#define CP_WAIT0()  asm volatile("cp.async.wait_group 0;" ::: "memory")

// ============================================================================
// Projection GEMM v13: 3-stage cp.async pipeline, 2 CTAs/SM.
// BM=128 BN=128 BK=64, 256 threads / 8 warps (2x4), warp tile 64x32.
// ============================================================================
constexpr int P_BM = 128, P_BN = 128, P_BK = 64, P_LD = 72;  // halves; 144B rows
constexpr int A_BYTES = P_BM * P_LD * 2;       // 18432
constexpr int BUFB    = 2 * A_BYTES;           // A + B = 36864
constexpr int SMEM_PROJ = 3 * BUFB;            // 110592 (3 stages)
constexpr int NTILE_M = NXP / P_BM;            // 261
constexpr int NKT = D_ / P_BK;                 // 8

__global__ __launch_bounds__(256, 2) void proj_gemm_all()
{
    extern __shared__ __half smh[];
    const uint32_t sbase = smem_u32(smh);

    const int tid  = threadIdx.x;
    const int warp = tid >> 5;
    const int lane = tid & 31;
    const int wr   = warp >> 2;
    const int wc   = warp & 3;
    const int tm   = blockIdx.x;
    const int tn   = blockIdx.y;
    const int mat  = blockIdx.z;

    const __half* Wm = g_w[mat];

    wmma::fragment<wmma::accumulator, 16, 16, 16, float> acc[4][2];
#pragma unroll
    for (int i = 0; i < 4; i++)
#pragma unroll
        for (int j = 0; j < 2; j++) wmma::fill_fragment(acc[i][j], 0.0f);

    auto copyTile = [&](int kt, int buf) {
        const int k0 = kt * P_BK;
        const uint32_t Ab = sbase + buf * BUFB;
        const uint32_t Bb = Ab + A_BYTES;
#pragma unroll
        for (int i = 0; i < 4; i++) {
            int id = tid + i * 256;
            int r = id >> 3, c = (id & 7) * 8;
            cp16(Ab + r * (P_LD * 2) + c * 2, g_x + (size_t)(tm * P_BM + r) * D_ + k0 + c);
        }
#pragma unroll
        for (int i = 0; i < 4; i++) {
            int id = tid + i * 256;
            int r = id >> 3, c = (id & 7) * 8;
            cp16(Bb + r * (P_LD * 2) + c * 2, Wm + (size_t)(tn * P_BN + r) * D_ + k0 + c);
        }
    };

    copyTile(0, 0);
    CP_COMMIT();
    copyTile(1, 1);
    CP_COMMIT();

    int buf = 0;
    for (int kt = 0; kt < NKT; kt++) {
        CP_WAIT1();                    // tile kt resident (kt+1 may be in flight)
        __syncthreads();
        if (kt + 2 < NKT) {
            copyTile(kt + 2, (buf + 2) % 3);
            CP_COMMIT();
        }
        const __half* As = smh + buf * (BUFB / 2);
        const __half* Bs = As + A_BYTES / 2;
#pragma unroll
        for (int kk = 0; kk < P_BK; kk += 16) {
            wmma::fragment<wmma::matrix_a, 16, 16, 16, __half, wmma::row_major> af[4];
#pragma unroll
            for (int i = 0; i < 4; i++)
                wmma::load_matrix_sync(af[i], &As[(wr * 64 + i * 16) * P_LD + kk], P_LD);
#pragma unroll
            for (int j = 0; j < 2; j++) {
                wmma::fragment<wmma::matrix_b, 16, 16, 16, __half, wmma::col_major> bf;
                wmma::load_matrix_sync(bf, &Bs[(wc * 32 + j * 16) * P_LD + kk], P_LD);
#pragma unroll
                for (int i = 0; i < 4; i++)
                    wmma::mma_sync(acc[i][j], af[i], bf, acc[i][j]);
            }
        }
        buf = (buf + 1) % 3;
        if (kt + 2 >= NKT) { CP_WAIT0(); }   // drain before last tiles reuse
    }
    __syncthreads();

    {
        float* pw = reinterpret_cast<float*>(smh) + warp * (16 * 20);
        const int pr = lane >> 1;
        const int pc = (lane & 1) * 8;
#pragma unroll
        for (int i = 0; i < 4; i++) {
            int row0 = tm * P_BM + wr * 64 + i * 16;
            if (row0 + 16 > NXR) continue;
            __half* Out;
            size_t rbase;
            if (row0 < NTT) { Out = g_tt[mat]; rbase = row0; }
            else            { Out = g_ss[mat]; rbase = row0 - NTT; }
#pragma unroll
            for (int j = 0; j < 2; j++) {
                wmma::store_matrix_sync(pw, acc[i][j], 20, wmma::mem_row_major);
                __syncwarp();
                float4 a = *reinterpret_cast<const float4*>(&pw[pr * 20 + pc]);
                float4 b = *reinterpret_cast<const float4*>(&pw[pr * 20 + pc + 4]);
                union { uint4 u; __half2 h[4]; } pk;
                pk.h[0] = __floats2half2_rn(a.x, a.y);
                pk.h[1] = __floats2half2_rn(a.z, a.w);
                pk.h[2] = __floats2half2_rn(b.x, b.y);
                pk.h[3] = __floats2half2_rn(b.z, b.w);
                *reinterpret_cast<uint4*>(
                    &Out[(rbase + pr) * D_ + tn * P_BN + wc * 32 + j * 16 + pc]) = pk.u;
                __syncwarp();
            }
        }
    }
}

// ============================================================================
// Fused attention kernel. grid = (7, 8, 8), 256 threads.
//   blockIdx.x < 4  : temporal chunk of 128 l's
//   blockIdx.x >= 4 : others chunk of 24 query rows
// ============================================================================
constexpr int ST  = 72;
constexpr int SPD = 132;
constexpr int PHD = 136;
constexpr int SMEM_ATT =
    64 * ST * 2 + 128 * ST * 2 + 128 * ST * 2
  + 64 * SPD * 4 + 64 * PHD * 2 + 3 * 64 * 4;

__device__ __forceinline__ void temporal_attn_body(
    char* smc, const float* bq, const float* bk, const float* bv, float* out)
{
    __half* Ql  = reinterpret_cast<__half*>(smc);
    __half* Kst = Ql  + 64 * ST;
    __half* Vst = Kst + 128 * ST;
    float*  SP  = reinterpret_cast<float*>(Vst + 128 * ST);
    __half* Ph  = reinterpret_cast<__half*>(SP + 64 * SPD);
    float*  bqs = reinterpret_cast<float*>(Ph + 64 * PHD);
    float*  bks = bqs + 64;
    float*  bvs = bks + 64;

    const int tid  = threadIdx.x;
    const int warp = tid >> 5;
    const int lane = tid & 31;
    const int b  = blockIdx.z, h = blockIdx.y;
    const int l0 = blockIdx.x * 128;
    const int cb = h * DH_;
    const int c4 = (tid & 15) * 4;

    if (tid < 64) {
        bqs[tid] = bq[cb + tid];
        bks[tid] = bk[cb + tid];
        bvs[tid] = bv[cb + tid];
    }
    // zero P cols 0..63 once
    for (int idx = tid; idx < 64 * 32; idx += 256) {
        int r = idx >> 5, c = (idx & 31) * 2;
        *reinterpret_cast<__half2*>(&Ph[r * PHD + c]) = __floats2half2_rn(0.f, 0.f);
    }
    __syncthreads();

    const __half2 bq01 = __floats2half2_rn(bqs[c4],     bqs[c4 + 1]);
    const __half2 bq23 = __floats2half2_rn(bqs[c4 + 2], bqs[c4 + 3]);
    const __half2 bk01 = __floats2half2_rn(bks[c4],     bks[c4 + 1]);
    const __half2 bk23 = __floats2half2_rn(bks[c4 + 2], bks[c4 + 3]);
    const __half2 bv01 = __floats2half2_rn(bvs[c4],     bvs[c4 + 1]);
    const __half2 bv23 = __floats2half2_rn(bvs[c4 + 2], bvs[c4 + 3]);

#pragma unroll
    for (int i = 0; i < 4; i++) {
        int idx = tid + i * 256;
        int o = idx >> 4;
        size_t srow = (size_t)(b * SS_ + 8 + o) * D_ + cb + c4;
        uint2 kr = *reinterpret_cast<const uint2*>(&g_ss[1][srow]);
        *reinterpret_cast<__half2*>(&Kst[(64 + o) * ST + c4])     = __hadd2(*reinterpret_cast<__half2*>(&kr.x), bk01);
        *reinterpret_cast<__half2*>(&Kst[(64 + o) * ST + c4 + 2]) = __hadd2(*reinterpret_cast<__half2*>(&kr.y), bk23);
        uint2 vr = *reinterpret_cast<const uint2*>(&g_ss[2][srow]);
        *reinterpret_cast<__half2*>(&Vst[(64 + o) * ST + c4])     = __hadd2(*reinterpret_cast<__half2*>(&vr.x), bv01);
        *reinterpret_cast<__half2*>(&Vst[(64 + o) * ST + c4 + 2]) = __hadd2(*reinterpret_cast<__half2*>(&vr.y), bv23);
    }

    // ---- register prefetch of iteration 0's Q/K/V ----
    uint2 pq[4], pk_[4], pv[4];
    auto prefetch = [&](int li0) {
        const size_t rbase = (size_t)b * 4096 + (size_t)(l0 + li0) * 8;
#pragma unroll
        for (int i = 0; i < 4; i++) {
            int idx = tid + i * 256;
            int r = idx >> 4;
            size_t off = (rbase + r) * D_ + cb + c4;
            pq[i]  = *reinterpret_cast<const uint2*>(&g_tt[0][off]);
            pk_[i] = *reinterpret_cast<const uint2*>(&g_tt[1][off]);
            pv[i]  = *reinterpret_cast<const uint2*>(&g_tt[2][off]);
        }
    };
    prefetch(0);
    __syncthreads();

    for (int li0 = 0; li0 < 128; li0 += 8) {
        // ---- stage from prefetch registers ----
#pragma unroll
        for (int i = 0; i < 4; i++) {
            int idx = tid + i * 256;
            int r = idx >> 4;
            *reinterpret_cast<__half2*>(&Ql[r * ST + c4])     = __hadd2(*reinterpret_cast<__half2*>(&pq[i].x), bq01);
            *reinterpret_cast<__half2*>(&Ql[r * ST + c4 + 2]) = __hadd2(*reinterpret_cast<__half2*>(&pq[i].y), bq23);
            *reinterpret_cast<__half2*>(&Kst[r * ST + c4])     = __hadd2(*reinterpret_cast<__half2*>(&pk_[i].x), bk01);
            *reinterpret_cast<__half2*>(&Kst[r * ST + c4 + 2]) = __hadd2(*reinterpret_cast<__half2*>(&pk_[i].y), bk23);
            *reinterpret_cast<__half2*>(&Vst[r * ST + c4])     = __hadd2(*reinterpret_cast<__half2*>(&pv[i].x), bv01);
            *reinterpret_cast<__half2*>(&Vst[r * ST + c4 + 2]) = __hadd2(*reinterpret_cast<__half2*>(&pv[i].y), bv23);
        }
        __syncthreads();

        if (li0 + 8 < 128) prefetch(li0 + 8);

        // ---- S = Q . Kst^T (64x128) ----
        {
            const int rt = warp >> 1;
            const int ct0 = (warp & 1) * 4;
            wmma::fragment<wmma::accumulator, 16, 16, 16, float> sacc[4];
#pragma unroll
            for (int j = 0; j < 4; j++) wmma::fill_fragment(sacc[j], 0.0f);
#pragma unroll
            for (int ks = 0; ks < 4; ks++) {
                wmma::fragment<wmma::matrix_a, 16, 16, 16, __half, wmma::row_major> af;
                wmma::load_matrix_sync(af, &Ql[(rt * 16) * ST + ks * 16], ST);
#pragma unroll
                for (int j = 0; j < 4; j++) {
                    wmma::fragment<wmma::matrix_b, 16, 16, 16, __half, wmma::col_major> bf;
                    wmma::load_matrix_sync(bf, &Kst[((ct0 + j) * 16) * ST + ks * 16], ST);
                    wmma::mma_sync(sacc[j], af, bf, sacc[j]);
                }
            }
#pragma unroll
            for (int j = 0; j < 4; j++)
                wmma::store_matrix_sync(&SP[(rt * 16) * SPD + (ct0 + j) * 16], sacc[j],
                                        SPD, wmma::mem_row_major);
        }
        __syncthreads();

        // ---- softmax (warp -> 8 rows, coalesced stores) ----
        for (int i = 0; i < 8; i++) {
            int r = warp * 8 + i;
            int li = r >> 3;
            float* Sr = &SP[r * SPD];
            __half* Pr = &Ph[r * PHD];
            float v0 = Sr[64 + lane] * 0.125f;
            float v1 = Sr[96 + lane] * 0.125f;
            float vs = (lane < 8) ? Sr[li * 8 + lane] * 0.125f : -3.4e38f;
            float mx = fmaxf(fmaxf(v0, v1), vs);
#pragma unroll
            for (int s = 16; s; s >>= 1) mx = fmaxf(mx, __shfl_xor_sync(0xffffffffu, mx, s));
            float e0 = __expf(v0 - mx), e1 = __expf(v1 - mx);
            float es = (lane < 8) ? __expf(vs - mx) : 0.f;
            float smv = e0 + e1 + es;
#pragma unroll
            for (int s = 16; s; s >>= 1) smv += __shfl_xor_sync(0xffffffffu, smv, s);
            float inv = 1.0f / smv;
            float p0 = e0 * inv, p1 = e1 * inv;
            size_t abase = OFF_TATT + ((size_t)(b * 8 + h) * 4096 + (size_t)(l0 + li0 + li) * 8 + (r & 7)) * 72;
            out[abase + 8 + lane]  = p0;
            out[abase + 40 + lane] = p1;
            float ps = es * inv;
            if (lane < 8) out[abase + lane] = ps;
            Pr[64 + lane] = __float2half_rn(p0);
            Pr[96 + lane] = __float2half_rn(p1);
            if (lane < 8) Pr[li * 8 + lane] = __float2half_rn(ps);
        }
        __syncthreads();

        // ---- Out = P . Vst (64x64) ----
        {
            const int rt = warp >> 1;
            const int ct0 = (warp & 1) * 2;
            wmma::fragment<wmma::accumulator, 16, 16, 16, float> oacc[2];
#pragma unroll
            for (int j = 0; j < 2; j++) wmma::fill_fragment(oacc[j], 0.0f);
#pragma unroll
            for (int ks = 0; ks < 8; ks++) {
                wmma::fragment<wmma::matrix_a, 16, 16, 16, __half, wmma::row_major> af;
                wmma::load_matrix_sync(af, &Ph[(rt * 16) * PHD + ks * 16], PHD);
#pragma unroll
                for (int j = 0; j < 2; j++) {
                    wmma::fragment<wmma::matrix_b, 16, 16, 16, __half, wmma::row_major> bf;
                    wmma::load_matrix_sync(bf, &Vst[(ks * 16) * ST + (ct0 + j) * 16], ST);
                    wmma::mma_sync(oacc[j], af, bf, oacc[j]);
                }
            }
            const size_t g0 = (size_t)(b * 4104 + 8 + (l0 + li0) * 8 + rt * 16);
#pragma unroll
            for (int j = 0; j < 2; j++)
                wmma::store_matrix_sync(out + g0 * D_ + cb + (ct0 + j) * 16, oacc[j],
                                        D_, wmma::mem_row_major);
        }
        __syncthreads();
    }
}

__device__ __forceinline__ void others_attn_body(
    char* smc, const float* bq, const float* bk, const float* bv, float* out)
{
    float* Qc  = reinterpret_cast<float*>(smc);
    float* KV  = Qc + 24 * 65;
    float* S   = KV + 72 * 65;
    float* bq_s = S + 24 * 73;
    float* bk_s = bq_s + 64;
    float* bv_s = bk_s + 64;

    const int tid = threadIdx.x;
    const int m0 = (blockIdx.x - 4) * 24;
    const int h = blockIdx.y, b = blockIdx.z;
    const int cb = h * DH_;

    if (tid < 64) {
        bq_s[tid] = bq[cb + tid];
        bk_s[tid] = bk[cb + tid];
        bv_s[tid] = bv[cb + tid];
    }
    __syncthreads();

    for (int idx = tid; idx < 72 * 64; idx += 256) {
        int n = idx >> 6, d = idx & 63;
        KV[n * 65 + d] = __half2float(g_ss[1][(size_t)(b * SS_ + n) * D_ + cb + d]) + bk_s[d];
    }
    for (int idx = tid; idx < 24 * 64; idx += 256) {
        int i = idx >> 6, d = idx & 63;
        Qc[i * 65 + d] = __half2float(g_ss[0][(size_t)(b * SS_ + m0 + i) * D_ + cb + d]) + bq_s[d];
    }
    __syncthreads();

    for (int e = tid; e < 24 * 72; e += 256) {
        int i = e / 72, n = e - i * 72;
        float acc = 0.f;
#pragma unroll
        for (int d = 0; d < 64; d++) acc = fmaf(Qc[i * 65 + d], KV[n * 65 + d], acc);
        S[i * 73 + n] = acc * 0.125f;
    }
    __syncthreads();

    {
        int w = tid >> 5, lane = tid & 31;
        for (int i = w; i < 24; i += 8) {
            float v0 = S[i * 73 + lane];
            float v1 = S[i * 73 + lane + 32];
            float v2 = (lane < 8) ? S[i * 73 + lane + 64] : -3.4e38f;
            float mx = fmaxf(fmaxf(v0, v1), v2);
#pragma unroll
            for (int s = 16; s; s >>= 1) mx = fmaxf(mx, __shfl_xor_sync(0xffffffffu, mx, s));
            float e0 = __expf(v0 - mx), e1 = __expf(v1 - mx);
            float e2 = (lane < 8) ? __expf(v2 - mx) : 0.f;
            float smv = e0 + e1 + e2;
#pragma unroll
            for (int s = 16; s; s >>= 1) smv += __shfl_xor_sync(0xffffffffu, smv, s);
            float inv = 1.0f / smv;
            size_t abase = OFF_OATT + ((size_t)(b * 8 + h) * 72 + (m0 + i)) * 72;
            float p0 = e0 * inv, p1 = e1 * inv;
            S[i * 73 + lane] = p0;       out[abase + lane]      = p0;
            S[i * 73 + lane + 32] = p1;  out[abase + lane + 32] = p1;
            if (lane < 8) {
                float p2 = e2 * inv;
                S[i * 73 + lane + 64] = p2;
                out[abase + lane + 64] = p2;
            }
        }
    }
    __syncthreads();

    for (int idx = tid; idx < 72 * 64; idx += 256) {
        int n = idx >> 6, d = idx & 63;
        KV[n * 65 + d] = __half2float(g_ss[2][(size_t)(b * SS_ + n) * D_ + cb + d]) + bv_s[d];
    }
    __syncthreads();

    for (int e = tid; e < 24 * 64; e += 256) {
        int i = e >> 6, d = e & 63;
        float acc = 0.f;
#pragma unroll
        for (int n = 0; n < 72; n++) acc = fmaf(S[i * 73 + n], KV[n * 65 + d], acc);
        int ng = m0 + i;
        int p = h * 4608 + ng * 64 + d;
        int j = p >> 9;
        int c = p & 511;
        if (j < 8)
            out[(size_t)(b * 4104 + j) * D_ + c] = acc;
        else
            out[OFF_OOUT + (size_t)(b * 64 + (j - 8)) * D_ + c] = acc;
    }
}

__global__ __launch_bounds__(256) void attn_fused_kernel(
    const float* __restrict__ bq, const float* __restrict__ bk,
    const float* __restrict__ bv, float* __restrict__ out)
{
    extern __shared__ char smc[];
    if (blockIdx.x < 4)
        temporal_attn_body(smc, bq, bk, bv, out);
    else
        others_attn_body(smc, bq, bk, bv, out);
}

// ============================================================================
extern "C" void kernel_launch(void* const* d_in, const int* in_sizes, int n_in,
                              void* d_out, int out_size)
{
    const float* Xt = (const float*)d_in[0];
    const float* Xo = (const float*)d_in[1];
    const float* Wq = (const float*)d_in[2];
    const float* bq = (const float*)d_in[3];
    const float* Wk = (const float*)d_in[4];
    const float* bk = (const float*)d_in[5];
    const float* Wv = (const float*)d_in[6];
    const float* bv = (const float*)d_in[7];
    float* out = (float*)d_out;

    cudaFuncSetAttribute((const void*)proj_gemm_all, cudaFuncAttributeMaxDynamicSharedMemorySize, SMEM_PROJ);
    cudaFuncSetAttribute((const void*)attn_fused_kernel, cudaFuncAttributeMaxDynamicSharedMemorySize, SMEM_ATT);

    convert_kernel<<<(NCONV + 255) / 256, 256>>>(Xt, Xo, Wq, Wk, Wv);
    proj_gemm_all<<<dim3(NTILE_M, D_ / P_BN, 3), 256, SMEM_PROJ>>>();
    attn_fused_kernel<<<dim3(7, 8, 8), 256, SMEM_ATT>>>(bq, bk, bv, out);
}

// round 15
// speedup vs baseline: 1.0293x; 1.0293x over previous
#include <cuda_runtime.h>
#include <cuda_fp16.h>
#include <mma.h>
#include <cstdint>

using namespace nvcuda;

// ---------------- problem constants ----------------
constexpr int B_  = 8;
constexpr int M_  = 8;
constexpr int D_  = 512;
constexpr int DH_ = 64;
constexpr int O_  = 64;
constexpr int SS_ = 72;    // M + O

constexpr int NTT = B_ * 512 * M_;  // 32768 temporal rows
constexpr int NSS = B_ * SS_;       // 576 ss rows
constexpr int NXR = NTT + NSS;      // 33344 gathered rows
constexpr int NXP = 33408;          // padded to 261*128

constexpr long long SZ_TOUT = (long long)B_ * 513 * M_ * D_;
constexpr long long SZ_OOUT = (long long)B_ * O_ * D_;
constexpr long long SZ_TATT = (long long)B_ * 8 * 512 * M_ * SS_;
constexpr long long OFF_OOUT = SZ_TOUT;
constexpr long long OFF_TATT = OFF_OOUT + SZ_OOUT;
constexpr long long OFF_OATT = OFF_TATT + SZ_TATT;

// ---------------- scratch ----------------
__device__ __half g_x[(size_t)NXP * D_];       // gathered fp16 inputs (rows >= NXR stay 0)
__device__ __half g_w[3][D_ * D_];             // fp16 weights
__device__ __half g_tt[3][(size_t)NTT * D_];   // Qtt, Ktt, Vtt (no bias)
__device__ __half g_ss[3][(size_t)NSS * D_];   // Qss, Kss, Vss (no bias)

// ============================================================================
// Prologue: fp32 -> fp16 convert + gather (X) and weight convert.
// ============================================================================
constexpr int NCHX = NXR * (D_ / 8);
constexpr int NCHW = 3 * D_ * (D_ / 8);
constexpr int NCONV = NCHX + NCHW;

__global__ __launch_bounds__(256) void convert_kernel(
    const float* __restrict__ Xt, const float* __restrict__ Xo,
    const float* __restrict__ Wq, const float* __restrict__ Wk,
    const float* __restrict__ Wv)
{
    int idx = blockIdx.x * 256 + threadIdx.x;
    if (idx >= NCONV) return;
    const float* src;
    __half* dst;
    if (idx < NCHX) {
        int r = idx >> 6;
        int c = (idx & 63) * 8;
        if (r < NTT) {
            src = Xt + (size_t)(r + ((r >> 12) << 3) + 8) * D_ + c;
        } else {
            int j = r - NTT;
            int bb = j / SS_;
            int jj = j - bb * SS_;
            src = ((jj < M_) ? (Xt + (size_t)(bb * 4104 + jj) * D_)
                             : (Xo + (size_t)(bb * O_ + jj - M_) * D_)) + c;
        }
        dst = g_x + (size_t)r * D_ + c;
    } else {
        int k = idx - NCHX;
        int mat = k / (D_ * 64);
        int rem = k - mat * (D_ * 64);
        int r = rem >> 6;
        int c = (rem & 63) * 8;
        const float* W = (mat == 0) ? Wq : ((mat == 1) ? Wk : Wv);
        src = W + (size_t)r * D_ + c;
        dst = g_w[mat] + (size_t)r * D_ + c;
    }
    float4 a = *reinterpret_cast<const float4*>(src);
    float4 b = *reinterpret_cast<const float4*>(src + 4);
    union { uint4 u; __half2 h[4]; } pk;
    pk.h[0] = __floats2half2_rn(a.x, a.y);
    pk.h[1] = __floats2half2_rn(a.z, a.w);
    pk.h[2] = __floats2half2_rn(b.x, b.y);
    pk.h[3] = __floats2half2_rn(b.z, b.w);
    *reinterpret_cast<uint4*>(dst) = pk.u;
}

// ---------------- cp.async helpers ----------------
__device__ __forceinline__ uint32_t smem_u32(const void* p) {
    uint32_t a;
    asm("{ .reg .u64 t; cvta.to.shared.u64 t, %1; cvt.u32.u64 %0, t; }" : "=r"(a) : "l"(p));
    return a;
}
__device__ __forceinline__ void cp16(uint32_t s, const void* g) {
    asm volatile("cp.async.cg.shared.global [%0], [%1], 16;" :: "r"(s), "l"(g) : "memory");
}
#define CP_COMMIT() asm volatile("cp.async.commit_group;" ::: "memory")
#define CP_WAIT0()  asm volatile("cp.async.wait_group 0;" ::: "memory")

// ============================================================================
// Projection GEMM (R12 exact, 2-stage): 2 CTAs/SM, BM=128 BN=128 BK=64.
// ============================================================================
constexpr int P_BM = 128, P_BN = 128, P_BK = 64, P_LD = 72;  // halves; 144B rows
constexpr int A_BYTES = P_BM * P_LD * 2;       // 18432
constexpr int BUFB    = 2 * A_BYTES;           // A + B = 36864
constexpr int SMEM_PROJ = 2 * BUFB;            // 73728
constexpr int NTILE_M = NXP / P_BM;            // 261

__global__ __launch_bounds__(256, 2) void proj_gemm_all()
{
    extern __shared__ __half smh[];
    const uint32_t sbase = smem_u32(smh);

    const int tid  = threadIdx.x;
    const int warp = tid >> 5;
    const int lane = tid & 31;
    const int wr   = warp >> 2;
    const int wc   = warp & 3;
    const int tm   = blockIdx.x;
    const int tn   = blockIdx.y;
    const int mat  = blockIdx.z;

    const __half* Wm = g_w[mat];

    wmma::fragment<wmma::accumulator, 16, 16, 16, float> acc[4][2];
#pragma unroll
    for (int i = 0; i < 4; i++)
#pragma unroll
        for (int j = 0; j < 2; j++) wmma::fill_fragment(acc[i][j], 0.0f);

    auto copyTile = [&](int kt, int buf) {
        const int k0 = kt * P_BK;
        const uint32_t Ab = sbase + buf * BUFB;
        const uint32_t Bb = Ab + A_BYTES;
#pragma unroll
        for (int i = 0; i < 4; i++) {
            int id = tid + i * 256;
            int r = id >> 3, c = (id & 7) * 8;
            cp16(Ab + r * (P_LD * 2) + c * 2, g_x + (size_t)(tm * P_BM + r) * D_ + k0 + c);
        }
#pragma unroll
        for (int i = 0; i < 4; i++) {
            int id = tid + i * 256;
            int r = id >> 3, c = (id & 7) * 8;
            cp16(Bb + r * (P_LD * 2) + c * 2, Wm + (size_t)(tn * P_BN + r) * D_ + k0 + c);
        }
    };

    copyTile(0, 0);
    CP_COMMIT();

    for (int kt = 0; kt < D_ / P_BK; kt++) {
        CP_WAIT0();
        __syncthreads();
        if (kt + 1 < D_ / P_BK) {
            copyTile(kt + 1, (kt + 1) & 1);
            CP_COMMIT();
        }
        const __half* As = smh + (kt & 1) * (BUFB / 2);
        const __half* Bs = As + A_BYTES / 2;
#pragma unroll
        for (int kk = 0; kk < P_BK; kk += 16) {
            wmma::fragment<wmma::matrix_a, 16, 16, 16, __half, wmma::row_major> af[4];
#pragma unroll
            for (int i = 0; i < 4; i++)
                wmma::load_matrix_sync(af[i], &As[(wr * 64 + i * 16) * P_LD + kk], P_LD);
#pragma unroll
            for (int j = 0; j < 2; j++) {
                wmma::fragment<wmma::matrix_b, 16, 16, 16, __half, wmma::col_major> bf;
                wmma::load_matrix_sync(bf, &Bs[(wc * 32 + j * 16) * P_LD + kk], P_LD);
#pragma unroll
                for (int i = 0; i < 4; i++)
                    wmma::mma_sync(acc[i][j], af[i], bf, acc[i][j]);
            }
        }
    }
    __syncthreads();

    {
        float* pw = reinterpret_cast<float*>(smh) + warp * (16 * 20);
        const int pr = lane >> 1;
        const int pc = (lane & 1) * 8;
#pragma unroll
        for (int i = 0; i < 4; i++) {
            int row0 = tm * P_BM + wr * 64 + i * 16;
            if (row0 + 16 > NXR) continue;
            __half* Out;
            size_t rbase;
            if (row0 < NTT) { Out = g_tt[mat]; rbase = row0; }
            else            { Out = g_ss[mat]; rbase = row0 - NTT; }
#pragma unroll
            for (int j = 0; j < 2; j++) {
                wmma::store_matrix_sync(pw, acc[i][j], 20, wmma::mem_row_major);
                __syncwarp();
                float4 a = *reinterpret_cast<const float4*>(&pw[pr * 20 + pc]);
                float4 b = *reinterpret_cast<const float4*>(&pw[pr * 20 + pc + 4]);
                union { uint4 u; __half2 h[4]; } pk;
                pk.h[0] = __floats2half2_rn(a.x, a.y);
                pk.h[1] = __floats2half2_rn(a.z, a.w);
                pk.h[2] = __floats2half2_rn(b.x, b.y);
                pk.h[3] = __floats2half2_rn(b.z, b.w);
                *reinterpret_cast<uint4*>(
                    &Out[(rbase + pr) * D_ + tn * P_BN + wc * 32 + j * 16 + pc]) = pk.u;
                __syncwarp();
            }
        }
    }
}

// ============================================================================
// Fused attention kernel. grid = (7, 8, 8), 256 threads.
//   blockIdx.x < 4  : temporal chunk of 128 l's
//   blockIdx.x >= 4 : others chunk of 24 query rows
// ============================================================================
constexpr int ST  = 72;
constexpr int SPD = 132;
constexpr int PHD = 136;
constexpr int SMEM_ATT =
    64 * ST * 2 + 128 * ST * 2 + 128 * ST * 2
  + 64 * SPD * 4 + 64 * PHD * 2 + 3 * 64 * 4;

__device__ __forceinline__ void temporal_attn_body(
    char* smc, const float* bq, const float* bk, const float* bv, float* out)
{
    __half* Ql  = reinterpret_cast<__half*>(smc);
    __half* Kst = Ql  + 64 * ST;
    __half* Vst = Kst + 128 * ST;
    float*  SP  = reinterpret_cast<float*>(Vst + 128 * ST);
    __half* Ph  = reinterpret_cast<__half*>(SP + 64 * SPD);
    float*  bqs = reinterpret_cast<float*>(Ph + 64 * PHD);
    float*  bks = bqs + 64;
    float*  bvs = bks + 64;

    const int tid  = threadIdx.x;
    const int warp = tid >> 5;
    const int lane = tid & 31;
    const int b  = blockIdx.z, h = blockIdx.y;
    const int l0 = blockIdx.x * 128;
    const int cb = h * DH_;
    const int c4 = (tid & 15) * 4;

    if (tid < 64) {
        bqs[tid] = bq[cb + tid];
        bks[tid] = bk[cb + tid];
        bvs[tid] = bv[cb + tid];
    }
    // zero P cols 0..63 once
    for (int idx = tid; idx < 64 * 32; idx += 256) {
        int r = idx >> 5, c = (idx & 31) * 2;
        *reinterpret_cast<__half2*>(&Ph[r * PHD + c]) = __floats2half2_rn(0.f, 0.f);
    }
    __syncthreads();

    const __half2 bq01 = __floats2half2_rn(bqs[c4],     bqs[c4 + 1]);
    const __half2 bq23 = __floats2half2_rn(bqs[c4 + 2], bqs[c4 + 3]);
    const __half2 bk01 = __floats2half2_rn(bks[c4],     bks[c4 + 1]);
    const __half2 bk23 = __floats2half2_rn(bks[c4 + 2], bks[c4 + 3]);
    const __half2 bv01 = __floats2half2_rn(bvs[c4],     bvs[c4 + 1]);
    const __half2 bv23 = __floats2half2_rn(bvs[c4 + 2], bvs[c4 + 3]);

#pragma unroll
    for (int i = 0; i < 4; i++) {
        int idx = tid + i * 256;
        int o = idx >> 4;
        size_t srow = (size_t)(b * SS_ + 8 + o) * D_ + cb + c4;
        uint2 kr = *reinterpret_cast<const uint2*>(&g_ss[1][srow]);
        *reinterpret_cast<__half2*>(&Kst[(64 + o) * ST + c4])     = __hadd2(*reinterpret_cast<__half2*>(&kr.x), bk01);
        *reinterpret_cast<__half2*>(&Kst[(64 + o) * ST + c4 + 2]) = __hadd2(*reinterpret_cast<__half2*>(&kr.y), bk23);
        uint2 vr = *reinterpret_cast<const uint2*>(&g_ss[2][srow]);
        *reinterpret_cast<__half2*>(&Vst[(64 + o) * ST + c4])     = __hadd2(*reinterpret_cast<__half2*>(&vr.x), bv01);
        *reinterpret_cast<__half2*>(&Vst[(64 + o) * ST + c4 + 2]) = __hadd2(*reinterpret_cast<__half2*>(&vr.y), bv23);
    }

    // ---- register prefetch of iteration 0's Q/K/V ----
    uint2 pq[4], pk_[4], pv[4];
    auto prefetch = [&](int li0) {
        const size_t rbase = (size_t)b * 4096 + (size_t)(l0 + li0) * 8;
#pragma unroll
        for (int i = 0; i < 4; i++) {
            int idx = tid + i * 256;
            int r = idx >> 4;
            size_t off = (rbase + r) * D_ + cb + c4;
            pq[i]  = *reinterpret_cast<const uint2*>(&g_tt[0][off]);
            pk_[i] = *reinterpret_cast<const uint2*>(&g_tt[1][off]);
            pv[i]  = *reinterpret_cast<const uint2*>(&g_tt[2][off]);
        }
    };
    prefetch(0);
    __syncthreads();

    for (int li0 = 0; li0 < 128; li0 += 8) {
        // ---- stage from prefetch registers ----
#pragma unroll
        for (int i = 0; i < 4; i++) {
            int idx = tid + i * 256;
            int r = idx >> 4;
            *reinterpret_cast<__half2*>(&Ql[r * ST + c4])     = __hadd2(*reinterpret_cast<__half2*>(&pq[i].x), bq01);
            *reinterpret_cast<__half2*>(&Ql[r * ST + c4 + 2]) = __hadd2(*reinterpret_cast<__half2*>(&pq[i].y), bq23);
            *reinterpret_cast<__half2*>(&Kst[r * ST + c4])     = __hadd2(*reinterpret_cast<__half2*>(&pk_[i].x), bk01);
            *reinterpret_cast<__half2*>(&Kst[r * ST + c4 + 2]) = __hadd2(*reinterpret_cast<__half2*>(&pk_[i].y), bk23);
            *reinterpret_cast<__half2*>(&Vst[r * ST + c4])     = __hadd2(*reinterpret_cast<__half2*>(&pv[i].x), bv01);
            *reinterpret_cast<__half2*>(&Vst[r * ST + c4 + 2]) = __hadd2(*reinterpret_cast<__half2*>(&pv[i].y), bv23);
        }
        __syncthreads();

        if (li0 + 8 < 128) prefetch(li0 + 8);

        // ---- S = Q . Kst^T (64x128) ----
        {
            const int rt = warp >> 1;
            const int ct0 = (warp & 1) * 4;
            wmma::fragment<wmma::accumulator, 16, 16, 16, float> sacc[4];
#pragma unroll
            for (int j = 0; j < 4; j++) wmma::fill_fragment(sacc[j], 0.0f);
#pragma unroll
            for (int ks = 0; ks < 4; ks++) {
                wmma::fragment<wmma::matrix_a, 16, 16, 16, __half, wmma::row_major> af;
                wmma::load_matrix_sync(af, &Ql[(rt * 16) * ST + ks * 16], ST);
#pragma unroll
                for (int j = 0; j < 4; j++) {
                    wmma::fragment<wmma::matrix_b, 16, 16, 16, __half, wmma::col_major> bf;
                    wmma::load_matrix_sync(bf, &Kst[((ct0 + j) * 16) * ST + ks * 16], ST);
                    wmma::mma_sync(sacc[j], af, bf, sacc[j]);
                }
            }
#pragma unroll
            for (int j = 0; j < 4; j++)
                wmma::store_matrix_sync(&SP[(rt * 16) * SPD + (ct0 + j) * 16], sacc[j],
                                        SPD, wmma::mem_row_major);
        }
        __syncthreads();

        // ---- softmax (warp -> 8 rows, coalesced stores) ----
        for (int i = 0; i < 8; i++) {
            int r = warp * 8 + i;
            int li = r >> 3;
            float* Sr = &SP[r * SPD];
            __half* Pr = &Ph[r * PHD];
            float v0 = Sr[64 + lane] * 0.125f;
            float v1 = Sr[96 + lane] * 0.125f;
            float vs = (lane < 8) ? Sr[li * 8 + lane] * 0.125f : -3.4e38f;
            float mx = fmaxf(fmaxf(v0, v1), vs);
#pragma unroll
            for (int s = 16; s; s >>= 1) mx = fmaxf(mx, __shfl_xor_sync(0xffffffffu, mx, s));
            float e0 = __expf(v0 - mx), e1 = __expf(v1 - mx);
            float es = (lane < 8) ? __expf(vs - mx) : 0.f;
            float smv = e0 + e1 + es;
#pragma unroll
            for (int s = 16; s; s >>= 1) smv += __shfl_xor_sync(0xffffffffu, smv, s);
            float inv = 1.0f / smv;
            float p0 = e0 * inv, p1 = e1 * inv;
            size_t abase = OFF_TATT + ((size_t)(b * 8 + h) * 4096 + (size_t)(l0 + li0 + li) * 8 + (r & 7)) * 72;
            out[abase + 8 + lane]  = p0;
            out[abase + 40 + lane] = p1;
            float ps = es * inv;
            if (lane < 8) out[abase + lane] = ps;
            Pr[64 + lane] = __float2half_rn(p0);
            Pr[96 + lane] = __float2half_rn(p1);
            if (lane < 8) Pr[li * 8 + lane] = __float2half_rn(ps);
        }
        __syncthreads();

        // ---- Out = P . Vst (64x64) ----
        {
            const int rt = warp >> 1;
            const int ct0 = (warp & 1) * 2;
            wmma::fragment<wmma::accumulator, 16, 16, 16, float> oacc[2];
#pragma unroll
            for (int j = 0; j < 2; j++) wmma::fill_fragment(oacc[j], 0.0f);
#pragma unroll
            for (int ks = 0; ks < 8; ks++) {
                wmma::fragment<wmma::matrix_a, 16, 16, 16, __half, wmma::row_major> af;
                wmma::load_matrix_sync(af, &Ph[(rt * 16) * PHD + ks * 16], PHD);
#pragma unroll
                for (int j = 0; j < 2; j++) {
                    wmma::fragment<wmma::matrix_b, 16, 16, 16, __half, wmma::row_major> bf;
                    wmma::load_matrix_sync(bf, &Vst[(ks * 16) * ST + (ct0 + j) * 16], ST);
                    wmma::mma_sync(oacc[j], af, bf, oacc[j]);
                }
            }
            const size_t g0 = (size_t)(b * 4104 + 8 + (l0 + li0) * 8 + rt * 16);
#pragma unroll
            for (int j = 0; j < 2; j++)
                wmma::store_matrix_sync(out + g0 * D_ + cb + (ct0 + j) * 16, oacc[j],
                                        D_, wmma::mem_row_major);
        }
        __syncthreads();
    }
}

__device__ __forceinline__ void others_attn_body(
    char* smc, const float* bq, const float* bk, const float* bv, float* out)
{
    float* Qc  = reinterpret_cast<float*>(smc);
    float* KV  = Qc + 24 * 65;
    float* S   = KV + 72 * 65;
    float* bq_s = S + 24 * 73;
    float* bk_s = bq_s + 64;
    float* bv_s = bk_s + 64;

    const int tid = threadIdx.x;
    const int m0 = (blockIdx.x - 4) * 24;
    const int h = blockIdx.y, b = blockIdx.z;
    const int cb = h * DH_;

    if (tid < 64) {
        bq_s[tid] = bq[cb + tid];
        bk_s[tid] = bk[cb + tid];
        bv_s[tid] = bv[cb + tid];
    }
    __syncthreads();

    for (int idx = tid; idx < 72 * 64; idx += 256) {
        int n = idx >> 6, d = idx & 63;
        KV[n * 65 + d] = __half2float(g_ss[1][(size_t)(b * SS_ + n) * D_ + cb + d]) + bk_s[d];
    }
    for (int idx = tid; idx < 24 * 64; idx += 256) {
        int i = idx >> 6, d = idx & 63;
        Qc[i * 65 + d] = __half2float(g_ss[0][(size_t)(b * SS_ + m0 + i) * D_ + cb + d]) + bq_s[d];
    }
    __syncthreads();

    for (int e = tid; e < 24 * 72; e += 256) {
        int i = e / 72, n = e - i * 72;
        float acc = 0.f;
#pragma unroll
        for (int d = 0; d < 64; d++) acc = fmaf(Qc[i * 65 + d], KV[n * 65 + d], acc);
        S[i * 73 + n] = acc * 0.125f;
    }
    __syncthreads();

    {
        int w = tid >> 5, lane = tid & 31;
        for (int i = w; i < 24; i += 8) {
            float v0 = S[i * 73 + lane];
            float v1 = S[i * 73 + lane + 32];
            float v2 = (lane < 8) ? S[i * 73 + lane + 64] : -3.4e38f;
            float mx = fmaxf(fmaxf(v0, v1), v2);
#pragma unroll
            for (int s = 16; s; s >>= 1) mx = fmaxf(mx, __shfl_xor_sync(0xffffffffu, mx, s));
            float e0 = __expf(v0 - mx), e1 = __expf(v1 - mx);
            float e2 = (lane < 8) ? __expf(v2 - mx) : 0.f;
            float smv = e0 + e1 + e2;
#pragma unroll
            for (int s = 16; s; s >>= 1) smv += __shfl_xor_sync(0xffffffffu, smv, s);
            float inv = 1.0f / smv;
            size_t abase = OFF_OATT + ((size_t)(b * 8 + h) * 72 + (m0 + i)) * 72;
            float p0 = e0 * inv, p1 = e1 * inv;
            S[i * 73 + lane] = p0;       out[abase + lane]      = p0;
            S[i * 73 + lane + 32] = p1;  out[abase + lane + 32] = p1;
            if (lane < 8) {
                float p2 = e2 * inv;
                S[i * 73 + lane + 64] = p2;
                out[abase + lane + 64] = p2;
            }
        }
    }
    __syncthreads();

    for (int idx = tid; idx < 72 * 64; idx += 256) {
        int n = idx >> 6, d = idx & 63;
        KV[n * 65 + d] = __half2float(g_ss[2][(size_t)(b * SS_ + n) * D_ + cb + d]) + bv_s[d];
    }
    __syncthreads();

    for (int e = tid; e < 24 * 64; e += 256) {
        int i = e >> 6, d = e & 63;
        float acc = 0.f;
#pragma unroll
        for (int n = 0; n < 72; n++) acc = fmaf(S[i * 73 + n], KV[n * 65 + d], acc);
        int ng = m0 + i;
        int p = h * 4608 + ng * 64 + d;
        int j = p >> 9;
        int c = p & 511;
        if (j < 8)
            out[(size_t)(b * 4104 + j) * D_ + c] = acc;
        else
            out[OFF_OOUT + (size_t)(b * 64 + (j - 8)) * D_ + c] = acc;
    }
}

__global__ __launch_bounds__(256) void attn_fused_kernel(
    const float* __restrict__ bq, const float* __restrict__ bk,
    const float* __restrict__ bv, float* __restrict__ out)
{
    extern __shared__ char smc[];
    if (blockIdx.x < 4)
        temporal_attn_body(smc, bq, bk, bv, out);
    else
        others_attn_body(smc, bq, bk, bv, out);
}

// ============================================================================
extern "C" void kernel_launch(void* const* d_in, const int* in_sizes, int n_in,
                              void* d_out, int out_size)
{
    const float* Xt = (const float*)d_in[0];
    const float* Xo = (const float*)d_in[1];
    const float* Wq = (const float*)d_in[2];
    const float* bq = (const float*)d_in[3];
    const float* Wk = (const float*)d_in[4];
    const float* bk = (const float*)d_in[5];
    const float* Wv = (const float*)d_in[6];
    const float* bv = (const float*)d_in[7];
    float* out = (float*)d_out;

    cudaFuncSetAttribute((const void*)proj_gemm_all, cudaFuncAttributeMaxDynamicSharedMemorySize, SMEM_PROJ);
    cudaFuncSetAttribute((const void*)attn_fused_kernel, cudaFuncAttributeMaxDynamicSharedMemorySize, SMEM_ATT);

    convert_kernel<<<(NCONV + 255) / 256, 256>>>(Xt, Xo, Wq, Wk, Wv);
    proj_gemm_all<<<dim3(NTILE_M, D_ / P_BN, 3), 256, SMEM_PROJ>>>();
    attn_fused_kernel<<<dim3(7, 8, 8), 256, SMEM_ATT>>>(bq, bk, bv, out);
}

// round 16
// speedup vs baseline: 1.0814x; 1.0507x over previous
#include <cuda_runtime.h>
#include <cuda_fp16.h>
#include <mma.h>
#include <cstdint>

using namespace nvcuda;

// ---------------- problem constants ----------------
constexpr int B_  = 8;
constexpr int M_  = 8;
constexpr int D_  = 512;
constexpr int DH_ = 64;
constexpr int O_  = 64;
constexpr int SS_ = 72;    // M + O

constexpr int NTT = B_ * 512 * M_;  // 32768 temporal rows
constexpr int NSS = B_ * SS_;       // 576 ss rows
constexpr int NXR = NTT + NSS;      // 33344 gathered rows
constexpr int NXP = 33408;          // padded to 261*128

constexpr long long SZ_TOUT = (long long)B_ * 513 * M_ * D_;
constexpr long long SZ_OOUT = (long long)B_ * O_ * D_;
constexpr long long SZ_TATT = (long long)B_ * 8 * 512 * M_ * SS_;
constexpr long long OFF_OOUT = SZ_TOUT;
constexpr long long OFF_TATT = OFF_OOUT + SZ_OOUT;
constexpr long long OFF_OATT = OFF_TATT + SZ_TATT;

// ---------------- scratch ----------------
__device__ __half g_x[(size_t)NXP * D_];       // gathered fp16 inputs (rows >= NXR stay 0)
__device__ __half g_w[3][D_ * D_];             // fp16 weights
__device__ __half g_tt[3][(size_t)NTT * D_];   // Qtt, Ktt, Vtt (no bias)
__device__ __half g_ss[3][(size_t)NSS * D_];   // Qss, Kss, Vss (no bias)

// ============================================================================
// Prologue: fp32 -> fp16 convert + gather (X) and weight convert.
// ============================================================================
constexpr int NCHX = NXR * (D_ / 8);
constexpr int NCHW = 3 * D_ * (D_ / 8);
constexpr int NCONV = NCHX + NCHW;

__global__ __launch_bounds__(256) void convert_kernel(
    const float* __restrict__ Xt, const float* __restrict__ Xo,
    const float* __restrict__ Wq, const float* __restrict__ Wk,
    const float* __restrict__ Wv)
{
    int idx = blockIdx.x * 256 + threadIdx.x;
    if (idx >= NCONV) return;
    const float* src;
    __half* dst;
    if (idx < NCHX) {
        int r = idx >> 6;
        int c = (idx & 63) * 8;
        if (r < NTT) {
            src = Xt + (size_t)(r + ((r >> 12) << 3) + 8) * D_ + c;
        } else {
            int j = r - NTT;
            int bb = j / SS_;
            int jj = j - bb * SS_;
            src = ((jj < M_) ? (Xt + (size_t)(bb * 4104 + jj) * D_)
                             : (Xo + (size_t)(bb * O_ + jj - M_) * D_)) + c;
        }
        dst = g_x + (size_t)r * D_ + c;
    } else {
        int k = idx - NCHX;
        int mat = k / (D_ * 64);
        int rem = k - mat * (D_ * 64);
        int r = rem >> 6;
        int c = (rem & 63) * 8;
        const float* W = (mat == 0) ? Wq : ((mat == 1) ? Wk : Wv);
        src = W + (size_t)r * D_ + c;
        dst = g_w[mat] + (size_t)r * D_ + c;
    }
    float4 a = *reinterpret_cast<const float4*>(src);
    float4 b = *reinterpret_cast<const float4*>(src + 4);
    union { uint4 u; __half2 h[4]; } pk;
    pk.h[0] = __floats2half2_rn(a.x, a.y);
    pk.h[1] = __floats2half2_rn(a.z, a.w);
    pk.h[2] = __floats2half2_rn(b.x, b.y);
    pk.h[3] = __floats2half2_rn(b.z, b.w);
    *reinterpret_cast<uint4*>(dst) = pk.u;
}

// ---------------- cp.async helpers ----------------
__device__ __forceinline__ uint32_t smem_u32(const void* p) {
    uint32_t a;
    asm("{ .reg .u64 t; cvta.to.shared.u64 t, %1; cvt.u32.u64 %0, t; }" : "=r"(a) : "l"(p));
    return a;
}
__device__ __forceinline__ void cp16(uint32_t s, const void* g) {
    asm volatile("cp.async.cg.shared.global [%0], [%1], 16;" :: "r"(s), "l"(g) : "memory");
}
#define CP_COMMIT() asm volatile("cp.async.commit_group;" ::: "memory")
#define CP_WAIT0()  asm volatile("cp.async.wait_group 0;" ::: "memory")

// ============================================================================
// Projection GEMM (R12 exact): 2-stage cp.async, 2 CTAs/SM, BM=128 BN=128 BK=64.
// ============================================================================
constexpr int P_BM = 128, P_BN = 128, P_BK = 64, P_LD = 72;  // halves; 144B rows
constexpr int A_BYTES = P_BM * P_LD * 2;       // 18432
constexpr int BUFB    = 2 * A_BYTES;           // A + B = 36864
constexpr int SMEM_PROJ = 2 * BUFB;            // 73728
constexpr int NTILE_M = NXP / P_BM;            // 261

__global__ __launch_bounds__(256, 2) void proj_gemm_all()
{
    extern __shared__ __half smh[];
    const uint32_t sbase = smem_u32(smh);

    const int tid  = threadIdx.x;
    const int warp = tid >> 5;
    const int lane = tid & 31;
    const int wr   = warp >> 2;
    const int wc   = warp & 3;
    const int tm   = blockIdx.x;
    const int tn   = blockIdx.y;
    const int mat  = blockIdx.z;

    const __half* Wm = g_w[mat];

    wmma::fragment<wmma::accumulator, 16, 16, 16, float> acc[4][2];
#pragma unroll
    for (int i = 0; i < 4; i++)
#pragma unroll
        for (int j = 0; j < 2; j++) wmma::fill_fragment(acc[i][j], 0.0f);

    auto copyTile = [&](int kt, int buf) {
        const int k0 = kt * P_BK;
        const uint32_t Ab = sbase + buf * BUFB;
        const uint32_t Bb = Ab + A_BYTES;
#pragma unroll
        for (int i = 0; i < 4; i++) {
            int id = tid + i * 256;
            int r = id >> 3, c = (id & 7) * 8;
            cp16(Ab + r * (P_LD * 2) + c * 2, g_x + (size_t)(tm * P_BM + r) * D_ + k0 + c);
        }
#pragma unroll
        for (int i = 0; i < 4; i++) {
            int id = tid + i * 256;
            int r = id >> 3, c = (id & 7) * 8;
            cp16(Bb + r * (P_LD * 2) + c * 2, Wm + (size_t)(tn * P_BN + r) * D_ + k0 + c);
        }
    };

    copyTile(0, 0);
    CP_COMMIT();

    for (int kt = 0; kt < D_ / P_BK; kt++) {
        CP_WAIT0();
        __syncthreads();
        if (kt + 1 < D_ / P_BK) {
            copyTile(kt + 1, (kt + 1) & 1);
            CP_COMMIT();
        }
        const __half* As = smh + (kt & 1) * (BUFB / 2);
        const __half* Bs = As + A_BYTES / 2;
#pragma unroll
        for (int kk = 0; kk < P_BK; kk += 16) {
            wmma::fragment<wmma::matrix_a, 16, 16, 16, __half, wmma::row_major> af[4];
#pragma unroll
            for (int i = 0; i < 4; i++)
                wmma::load_matrix_sync(af[i], &As[(wr * 64 + i * 16) * P_LD + kk], P_LD);
#pragma unroll
            for (int j = 0; j < 2; j++) {
                wmma::fragment<wmma::matrix_b, 16, 16, 16, __half, wmma::col_major> bf;
                wmma::load_matrix_sync(bf, &Bs[(wc * 32 + j * 16) * P_LD + kk], P_LD);
#pragma unroll
                for (int i = 0; i < 4; i++)
                    wmma::mma_sync(acc[i][j], af[i], bf, acc[i][j]);
            }
        }
    }
    __syncthreads();

    {
        float* pw = reinterpret_cast<float*>(smh) + warp * (16 * 20);
        const int pr = lane >> 1;
        const int pc = (lane & 1) * 8;
#pragma unroll
        for (int i = 0; i < 4; i++) {
            int row0 = tm * P_BM + wr * 64 + i * 16;
            if (row0 + 16 > NXR) continue;
            __half* Out;
            size_t rbase;
            if (row0 < NTT) { Out = g_tt[mat]; rbase = row0; }
            else            { Out = g_ss[mat]; rbase = row0 - NTT; }
#pragma unroll
            for (int j = 0; j < 2; j++) {
                wmma::store_matrix_sync(pw, acc[i][j], 20, wmma::mem_row_major);
                __syncwarp();
                float4 a = *reinterpret_cast<const float4*>(&pw[pr * 20 + pc]);
                float4 b = *reinterpret_cast<const float4*>(&pw[pr * 20 + pc + 4]);
                union { uint4 u; __half2 h[4]; } pk;
                pk.h[0] = __floats2half2_rn(a.x, a.y);
                pk.h[1] = __floats2half2_rn(a.z, a.w);
                pk.h[2] = __floats2half2_rn(b.x, b.y);
                pk.h[3] = __floats2half2_rn(b.z, b.w);
                *reinterpret_cast<uint4*>(
                    &Out[(rbase + pr) * D_ + tn * P_BN + wc * 32 + j * 16 + pc]) = pk.u;
                __syncwarp();
            }
        }
    }
}

// ============================================================================
// Fused attention kernel (R12 structure). grid = (11, 8, 8), 256 threads.
//   blockIdx.x < 8  : temporal chunk of 64 l's
//   blockIdx.x >= 8 : others chunk of 24 query rows
// Attention-prob stores use streaming (.cs) hints — outputs are never re-read,
// keeping g_tt resident in L2.
// ============================================================================
constexpr int ST  = 72;
constexpr int SPD = 132;
constexpr int PHD = 136;
constexpr int SMEM_ATT =
    64 * ST * 2 + 128 * ST * 2 + 128 * ST * 2
  + 64 * SPD * 4 + 64 * PHD * 2 + 3 * 64 * 4;

__device__ __forceinline__ void temporal_attn_body(
    char* smc, const float* bq, const float* bk, const float* bv, float* out)
{
    __half* Ql  = reinterpret_cast<__half*>(smc);
    __half* Kst = Ql  + 64 * ST;
    __half* Vst = Kst + 128 * ST;
    float*  SP  = reinterpret_cast<float*>(Vst + 128 * ST);
    __half* Ph  = reinterpret_cast<__half*>(SP + 64 * SPD);
    float*  bqs = reinterpret_cast<float*>(Ph + 64 * PHD);
    float*  bks = bqs + 64;
    float*  bvs = bks + 64;

    const int tid  = threadIdx.x;
    const int warp = tid >> 5;
    const int lane = tid & 31;
    const int b  = blockIdx.z, h = blockIdx.y;
    const int l0 = blockIdx.x * 64;
    const int cb = h * DH_;
    const int c4 = (tid & 15) * 4;

    if (tid < 64) {
        bqs[tid] = bq[cb + tid];
        bks[tid] = bk[cb + tid];
        bvs[tid] = bv[cb + tid];
    }
    // zero P cols 0..63 once
    for (int idx = tid; idx < 64 * 32; idx += 256) {
        int r = idx >> 5, c = (idx & 31) * 2;
        *reinterpret_cast<__half2*>(&Ph[r * PHD + c]) = __floats2half2_rn(0.f, 0.f);
    }
    __syncthreads();

    const __half2 bq01 = __floats2half2_rn(bqs[c4],     bqs[c4 + 1]);
    const __half2 bq23 = __floats2half2_rn(bqs[c4 + 2], bqs[c4 + 3]);
    const __half2 bk01 = __floats2half2_rn(bks[c4],     bks[c4 + 1]);
    const __half2 bk23 = __floats2half2_rn(bks[c4 + 2], bks[c4 + 3]);
    const __half2 bv01 = __floats2half2_rn(bvs[c4],     bvs[c4 + 1]);
    const __half2 bv23 = __floats2half2_rn(bvs[c4 + 2], bvs[c4 + 3]);

#pragma unroll
    for (int i = 0; i < 4; i++) {
        int idx = tid + i * 256;
        int o = idx >> 4;
        size_t srow = (size_t)(b * SS_ + 8 + o) * D_ + cb + c4;
        uint2 kr = *reinterpret_cast<const uint2*>(&g_ss[1][srow]);
        *reinterpret_cast<__half2*>(&Kst[(64 + o) * ST + c4])     = __hadd2(*reinterpret_cast<__half2*>(&kr.x), bk01);
        *reinterpret_cast<__half2*>(&Kst[(64 + o) * ST + c4 + 2]) = __hadd2(*reinterpret_cast<__half2*>(&kr.y), bk23);
        uint2 vr = *reinterpret_cast<const uint2*>(&g_ss[2][srow]);
        *reinterpret_cast<__half2*>(&Vst[(64 + o) * ST + c4])     = __hadd2(*reinterpret_cast<__half2*>(&vr.x), bv01);
        *reinterpret_cast<__half2*>(&Vst[(64 + o) * ST + c4 + 2]) = __hadd2(*reinterpret_cast<__half2*>(&vr.y), bv23);
    }

    // ---- register prefetch of iteration 0's Q/K/V ----
    uint2 pq[4], pk_[4], pv[4];
    auto prefetch = [&](int li0) {
        const size_t rbase = (size_t)b * 4096 + (size_t)(l0 + li0) * 8;
#pragma unroll
        for (int i = 0; i < 4; i++) {
            int idx = tid + i * 256;
            int r = idx >> 4;
            size_t off = (rbase + r) * D_ + cb + c4;
            pq[i]  = *reinterpret_cast<const uint2*>(&g_tt[0][off]);
            pk_[i] = *reinterpret_cast<const uint2*>(&g_tt[1][off]);
            pv[i]  = *reinterpret_cast<const uint2*>(&g_tt[2][off]);
        }
    };
    prefetch(0);
    __syncthreads();

    for (int li0 = 0; li0 < 64; li0 += 8) {
        // ---- stage from prefetch registers ----
#pragma unroll
        for (int i = 0; i < 4; i++) {
            int idx = tid + i * 256;
            int r = idx >> 4;
            *reinterpret_cast<__half2*>(&Ql[r * ST + c4])     = __hadd2(*reinterpret_cast<__half2*>(&pq[i].x), bq01);
            *reinterpret_cast<__half2*>(&Ql[r * ST + c4 + 2]) = __hadd2(*reinterpret_cast<__half2*>(&pq[i].y), bq23);
            *reinterpret_cast<__half2*>(&Kst[r * ST + c4])     = __hadd2(*reinterpret_cast<__half2*>(&pk_[i].x), bk01);
            *reinterpret_cast<__half2*>(&Kst[r * ST + c4 + 2]) = __hadd2(*reinterpret_cast<__half2*>(&pk_[i].y), bk23);
            *reinterpret_cast<__half2*>(&Vst[r * ST + c4])     = __hadd2(*reinterpret_cast<__half2*>(&pv[i].x), bv01);
            *reinterpret_cast<__half2*>(&Vst[r * ST + c4 + 2]) = __hadd2(*reinterpret_cast<__half2*>(&pv[i].y), bv23);
        }
        __syncthreads();

        if (li0 + 8 < 64) prefetch(li0 + 8);

        // ---- S = Q . Kst^T (64x128) ----
        {
            const int rt = warp >> 1;
            const int ct0 = (warp & 1) * 4;
            wmma::fragment<wmma::accumulator, 16, 16, 16, float> sacc[4];
#pragma unroll
            for (int j = 0; j < 4; j++) wmma::fill_fragment(sacc[j], 0.0f);
#pragma unroll
            for (int ks = 0; ks < 4; ks++) {
                wmma::fragment<wmma::matrix_a, 16, 16, 16, __half, wmma::row_major> af;
                wmma::load_matrix_sync(af, &Ql[(rt * 16) * ST + ks * 16], ST);
#pragma unroll
                for (int j = 0; j < 4; j++) {
                    wmma::fragment<wmma::matrix_b, 16, 16, 16, __half, wmma::col_major> bf;
                    wmma::load_matrix_sync(bf, &Kst[((ct0 + j) * 16) * ST + ks * 16], ST);
                    wmma::mma_sync(sacc[j], af, bf, sacc[j]);
                }
            }
#pragma unroll
            for (int j = 0; j < 4; j++)
                wmma::store_matrix_sync(&SP[(rt * 16) * SPD + (ct0 + j) * 16], sacc[j],
                                        SPD, wmma::mem_row_major);
        }
        __syncthreads();

        // ---- softmax (warp -> 8 rows, coalesced streaming stores) ----
        for (int i = 0; i < 8; i++) {
            int r = warp * 8 + i;
            int li = r >> 3;
            float* Sr = &SP[r * SPD];
            __half* Pr = &Ph[r * PHD];
            float v0 = Sr[64 + lane] * 0.125f;
            float v1 = Sr[96 + lane] * 0.125f;
            float vs = (lane < 8) ? Sr[li * 8 + lane] * 0.125f : -3.4e38f;
            float mx = fmaxf(fmaxf(v0, v1), vs);
#pragma unroll
            for (int s = 16; s; s >>= 1) mx = fmaxf(mx, __shfl_xor_sync(0xffffffffu, mx, s));
            float e0 = __expf(v0 - mx), e1 = __expf(v1 - mx);
            float es = (lane < 8) ? __expf(vs - mx) : 0.f;
            float smv = e0 + e1 + es;
#pragma unroll
            for (int s = 16; s; s >>= 1) smv += __shfl_xor_sync(0xffffffffu, smv, s);
            float inv = 1.0f / smv;
            float p0 = e0 * inv, p1 = e1 * inv;
            size_t abase = OFF_TATT + ((size_t)(b * 8 + h) * 4096 + (size_t)(l0 + li0 + li) * 8 + (r & 7)) * 72;
            __stcs(&out[abase + 8 + lane],  p0);
            __stcs(&out[abase + 40 + lane], p1);
            float ps = es * inv;
            if (lane < 8) __stcs(&out[abase + lane], ps);
            Pr[64 + lane] = __float2half_rn(p0);
            Pr[96 + lane] = __float2half_rn(p1);
            if (lane < 8) Pr[li * 8 + lane] = __float2half_rn(ps);
        }
        __syncthreads();

        // ---- Out = P . Vst (64x64) ----
        {
            const int rt = warp >> 1;
            const int ct0 = (warp & 1) * 2;
            wmma::fragment<wmma::accumulator, 16, 16, 16, float> oacc[2];
#pragma unroll
            for (int j = 0; j < 2; j++) wmma::fill_fragment(oacc[j], 0.0f);
#pragma unroll
            for (int ks = 0; ks < 8; ks++) {
                wmma::fragment<wmma::matrix_a, 16, 16, 16, __half, wmma::row_major> af;
                wmma::load_matrix_sync(af, &Ph[(rt * 16) * PHD + ks * 16], PHD);
#pragma unroll
                for (int j = 0; j < 2; j++) {
                    wmma::fragment<wmma::matrix_b, 16, 16, 16, __half, wmma::row_major> bf;
                    wmma::load_matrix_sync(bf, &Vst[(ks * 16) * ST + (ct0 + j) * 16], ST);
                    wmma::mma_sync(oacc[j], af, bf, oacc[j]);
                }
            }
            const size_t g0 = (size_t)(b * 4104 + 8 + (l0 + li0) * 8 + rt * 16);
#pragma unroll
            for (int j = 0; j < 2; j++)
                wmma::store_matrix_sync(out + g0 * D_ + cb + (ct0 + j) * 16, oacc[j],
                                        D_, wmma::mem_row_major);
        }
        __syncthreads();
    }
}

__device__ __forceinline__ void others_attn_body(
    char* smc, const float* bq, const float* bk, const float* bv, float* out)
{
    float* Qc  = reinterpret_cast<float*>(smc);
    float* KV  = Qc + 24 * 65;
    float* S   = KV + 72 * 65;
    float* bq_s = S + 24 * 73;
    float* bk_s = bq_s + 64;
    float* bv_s = bk_s + 64;

    const int tid = threadIdx.x;
    const int m0 = (blockIdx.x - 8) * 24;
    const int h = blockIdx.y, b = blockIdx.z;
    const int cb = h * DH_;

    if (tid < 64) {
        bq_s[tid] = bq[cb + tid];
        bk_s[tid] = bk[cb + tid];
        bv_s[tid] = bv[cb + tid];
    }
    __syncthreads();

    for (int idx = tid; idx < 72 * 64; idx += 256) {
        int n = idx >> 6, d = idx & 63;
        KV[n * 65 + d] = __half2float(g_ss[1][(size_t)(b * SS_ + n) * D_ + cb + d]) + bk_s[d];
    }
    for (int idx = tid; idx < 24 * 64; idx += 256) {
        int i = idx >> 6, d = idx & 63;
        Qc[i * 65 + d] = __half2float(g_ss[0][(size_t)(b * SS_ + m0 + i) * D_ + cb + d]) + bq_s[d];
    }
    __syncthreads();

    for (int e = tid; e < 24 * 72; e += 256) {
        int i = e / 72, n = e - i * 72;
        float acc = 0.f;
#pragma unroll
        for (int d = 0; d < 64; d++) acc = fmaf(Qc[i * 65 + d], KV[n * 65 + d], acc);
        S[i * 73 + n] = acc * 0.125f;
    }
    __syncthreads();

    {
        int w = tid >> 5, lane = tid & 31;
        for (int i = w; i < 24; i += 8) {
            float v0 = S[i * 73 + lane];
            float v1 = S[i * 73 + lane + 32];
            float v2 = (lane < 8) ? S[i * 73 + lane + 64] : -3.4e38f;
            float mx = fmaxf(fmaxf(v0, v1), v2);
#pragma unroll
            for (int s = 16; s; s >>= 1) mx = fmaxf(mx, __shfl_xor_sync(0xffffffffu, mx, s));
            float e0 = __expf(v0 - mx), e1 = __expf(v1 - mx);
            float e2 = (lane < 8) ? __expf(v2 - mx) : 0.f;
            float smv = e0 + e1 + e2;
#pragma unroll
            for (int s = 16; s; s >>= 1) smv += __shfl_xor_sync(0xffffffffu, smv, s);
            float inv = 1.0f / smv;
            size_t abase = OFF_OATT + ((size_t)(b * 8 + h) * 72 + (m0 + i)) * 72;
            float p0 = e0 * inv, p1 = e1 * inv;
            S[i * 73 + lane] = p0;       __stcs(&out[abase + lane],      p0);
            S[i * 73 + lane + 32] = p1;  __stcs(&out[abase + lane + 32], p1);
            if (lane < 8) {
                float p2 = e2 * inv;
                S[i * 73 + lane + 64] = p2;
                __stcs(&out[abase + lane + 64], p2);
            }
        }
    }
    __syncthreads();

    for (int idx = tid; idx < 72 * 64; idx += 256) {
        int n = idx >> 6, d = idx & 63;
        KV[n * 65 + d] = __half2float(g_ss[2][(size_t)(b * SS_ + n) * D_ + cb + d]) + bv_s[d];
    }
    __syncthreads();

    for (int e = tid; e < 24 * 64; e += 256) {
        int i = e >> 6, d = e & 63;
        float acc = 0.f;
#pragma unroll
        for (int n = 0; n < 72; n++) acc = fmaf(S[i * 73 + n], KV[n * 65 + d], acc);
        int ng = m0 + i;
        int p = h * 4608 + ng * 64 + d;
        int j = p >> 9;
        int c = p & 511;
        if (j < 8)
            out[(size_t)(b * 4104 + j) * D_ + c] = acc;
        else
            out[OFF_OOUT + (size_t)(b * 64 + (j - 8)) * D_ + c] = acc;
    }
}

__global__ __launch_bounds__(256) void attn_fused_kernel(
    const float* __restrict__ bq, const float* __restrict__ bk,
    const float* __restrict__ bv, float* __restrict__ out)
{
    extern __shared__ char smc[];
    if (blockIdx.x < 8)
        temporal_attn_body(smc, bq, bk, bv, out);
    else
        others_attn_body(smc, bq, bk, bv, out);
}

// ============================================================================
extern "C" void kernel_launch(void* const* d_in, const int* in_sizes, int n_in,
                              void* d_out, int out_size)
{
    const float* Xt = (const float*)d_in[0];
    const float* Xo = (const float*)d_in[1];
    const float* Wq = (const float*)d_in[2];
    const float* bq = (const float*)d_in[3];
    const float* Wk = (const float*)d_in[4];
    const float* bk = (const float*)d_in[5];
    const float* Wv = (const float*)d_in[6];
    const float* bv = (const float*)d_in[7];
    float* out = (float*)d_out;

    cudaFuncSetAttribute((const void*)proj_gemm_all, cudaFuncAttributeMaxDynamicSharedMemorySize, SMEM_PROJ);
    cudaFuncSetAttribute((const void*)attn_fused_kernel, cudaFuncAttributeMaxDynamicSharedMemorySize, SMEM_ATT);

    convert_kernel<<<(NCONV + 255) / 256, 256>>>(Xt, Xo, Wq, Wk, Wv);
    proj_gemm_all<<<dim3(NTILE_M, D_ / P_BN, 3), 256, SMEM_PROJ>>>();
    attn_fused_kernel<<<dim3(11, 8, 8), 256, SMEM_ATT>>>(bq, bk, bv, out);
}

// round 17
// speedup vs baseline: 1.1287x; 1.0437x over previous
#include <cuda_runtime.h>
#include <cuda_fp16.h>
#include <mma.h>
#include <cstdint>

using namespace nvcuda;

// ---------------- problem constants ----------------
constexpr int B_  = 8;
constexpr int M_  = 8;
constexpr int D_  = 512;
constexpr int DH_ = 64;
constexpr int O_  = 64;
constexpr int SS_ = 72;    // M + O

constexpr int NTT = B_ * 512 * M_;  // 32768 temporal rows
constexpr int NSS = B_ * SS_;       // 576 ss rows
constexpr int NXR = NTT + NSS;      // 33344 gathered rows
constexpr int NXP = 33408;          // padded to 261*128

constexpr long long SZ_TOUT = (long long)B_ * 513 * M_ * D_;
constexpr long long SZ_OOUT = (long long)B_ * O_ * D_;
constexpr long long SZ_TATT = (long long)B_ * 8 * 512 * M_ * SS_;
constexpr long long OFF_OOUT = SZ_TOUT;
constexpr long long OFF_TATT = OFF_OOUT + SZ_OOUT;
constexpr long long OFF_OATT = OFF_TATT + SZ_TATT;

// ---------------- scratch ----------------
__device__ __half g_x[(size_t)NXP * D_];
__device__ __half g_w[3][D_ * D_];
__device__ __half g_tt[3][(size_t)NTT * D_];
__device__ __half g_ss[3][(size_t)NSS * D_];

// ============================================================================
// Prologue: fp32 -> fp16 convert + gather.
// ============================================================================
constexpr int NCHX = NXR * (D_ / 8);
constexpr int NCHW = 3 * D_ * (D_ / 8);
constexpr int NCONV = NCHX + NCHW;

__global__ __launch_bounds__(256) void convert_kernel(
    const float* __restrict__ Xt, const float* __restrict__ Xo,
    const float* __restrict__ Wq, const float* __restrict__ Wk,
    const float* __restrict__ Wv)
{
    int idx = blockIdx.x * 256 + threadIdx.x;
    if (idx >= NCONV) return;
    const float* src;
    __half* dst;
    if (idx < NCHX) {
        int r = idx >> 6;
        int c = (idx & 63) * 8;
        if (r < NTT) {
            src = Xt + (size_t)(r + ((r >> 12) << 3) + 8) * D_ + c;
        } else {
            int j = r - NTT;
            int bb = j / SS_;
            int jj = j - bb * SS_;
            src = ((jj < M_) ? (Xt + (size_t)(bb * 4104 + jj) * D_)
                             : (Xo + (size_t)(bb * O_ + jj - M_) * D_)) + c;
        }
        dst = g_x + (size_t)r * D_ + c;
    } else {
        int k = idx - NCHX;
        int mat = k / (D_ * 64);
        int rem = k - mat * (D_ * 64);
        int r = rem >> 6;
        int c = (rem & 63) * 8;
        const float* W = (mat == 0) ? Wq : ((mat == 1) ? Wk : Wv);
        src = W + (size_t)r * D_ + c;
        dst = g_w[mat] + (size_t)r * D_ + c;
    }
    float4 a = *reinterpret_cast<const float4*>(src);
    float4 b = *reinterpret_cast<const float4*>(src + 4);
    union { uint4 u; __half2 h[4]; } pk;
    pk.h[0] = __floats2half2_rn(a.x, a.y);
    pk.h[1] = __floats2half2_rn(a.z, a.w);
    pk.h[2] = __floats2half2_rn(b.x, b.y);
    pk.h[3] = __floats2half2_rn(b.z, b.w);
    *reinterpret_cast<uint4*>(dst) = pk.u;
}

// ---------------- cp.async helpers ----------------
__device__ __forceinline__ uint32_t smem_u32(const void* p) {
    uint32_t a;
    asm("{ .reg .u64 t; cvta.to.shared.u64 t, %1; cvt.u32.u64 %0, t; }" : "=r"(a) : "l"(p));
    return a;
}
__device__ __forceinline__ void cp16(uint32_t s, const void* g) {
    asm volatile("cp.async.cg.shared.global [%0], [%1], 16;" :: "r"(s), "l"(g) : "memory");
}
#define CP_COMMIT() asm volatile("cp.async.commit_group;" ::: "memory")
#define CP_WAIT0()  asm volatile("cp.async.wait_group 0;" ::: "memory")

// ============================================================================
// Projection GEMM (R12 exact): 2-stage cp.async, 2 CTAs/SM, BM=128 BN=128 BK=64.
// ============================================================================
constexpr int P_BM = 128, P_BN = 128, P_BK = 64, P_LD = 72;
constexpr int A_BYTES = P_BM * P_LD * 2;
constexpr int BUFB    = 2 * A_BYTES;
constexpr int SMEM_PROJ = 2 * BUFB;
constexpr int NTILE_M = NXP / P_BM;

__global__ __launch_bounds__(256, 2) void proj_gemm_all()
{
    extern __shared__ __half smh[];
    const uint32_t sbase = smem_u32(smh);

    const int tid  = threadIdx.x;
    const int warp = tid >> 5;
    const int lane = tid & 31;
    const int wr   = warp >> 2;
    const int wc   = warp & 3;
    const int tm   = blockIdx.x;
    const int tn   = blockIdx.y;
    const int mat  = blockIdx.z;

    const __half* Wm = g_w[mat];

    wmma::fragment<wmma::accumulator, 16, 16, 16, float> acc[4][2];
#pragma unroll
    for (int i = 0; i < 4; i++)
#pragma unroll
        for (int j = 0; j < 2; j++) wmma::fill_fragment(acc[i][j], 0.0f);

    auto copyTile = [&](int kt, int buf) {
        const int k0 = kt * P_BK;
        const uint32_t Ab = sbase + buf * BUFB;
        const uint32_t Bb = Ab + A_BYTES;
#pragma unroll
        for (int i = 0; i < 4; i++) {
            int id = tid + i * 256;
            int r = id >> 3, c = (id & 7) * 8;
            cp16(Ab + r * (P_LD * 2) + c * 2, g_x + (size_t)(tm * P_BM + r) * D_ + k0 + c);
        }
#pragma unroll
        for (int i = 0; i < 4; i++) {
            int id = tid + i * 256;
            int r = id >> 3, c = (id & 7) * 8;
            cp16(Bb + r * (P_LD * 2) + c * 2, Wm + (size_t)(tn * P_BN + r) * D_ + k0 + c);
        }
    };

    copyTile(0, 0);
    CP_COMMIT();

    for (int kt = 0; kt < D_ / P_BK; kt++) {
        CP_WAIT0();
        __syncthreads();
        if (kt + 1 < D_ / P_BK) {
            copyTile(kt + 1, (kt + 1) & 1);
            CP_COMMIT();
        }
        const __half* As = smh + (kt & 1) * (BUFB / 2);
        const __half* Bs = As + A_BYTES / 2;
#pragma unroll
        for (int kk = 0; kk < P_BK; kk += 16) {
            wmma::fragment<wmma::matrix_a, 16, 16, 16, __half, wmma::row_major> af[4];
#pragma unroll
            for (int i = 0; i < 4; i++)
                wmma::load_matrix_sync(af[i], &As[(wr * 64 + i * 16) * P_LD + kk], P_LD);
#pragma unroll
            for (int j = 0; j < 2; j++) {
                wmma::fragment<wmma::matrix_b, 16, 16, 16, __half, wmma::col_major> bf;
                wmma::load_matrix_sync(bf, &Bs[(wc * 32 + j * 16) * P_LD + kk], P_LD);
#pragma unroll
                for (int i = 0; i < 4; i++)
                    wmma::mma_sync(acc[i][j], af[i], bf, acc[i][j]);
            }
        }
    }
    __syncthreads();

    {
        float* pw = reinterpret_cast<float*>(smh) + warp * (16 * 20);
        const int pr = lane >> 1;
        const int pc = (lane & 1) * 8;
#pragma unroll
        for (int i = 0; i < 4; i++) {
            int row0 = tm * P_BM + wr * 64 + i * 16;
            if (row0 + 16 > NXR) continue;
            __half* Out;
            size_t rbase;
            if (row0 < NTT) { Out = g_tt[mat]; rbase = row0; }
            else            { Out = g_ss[mat]; rbase = row0 - NTT; }
#pragma unroll
            for (int j = 0; j < 2; j++) {
                wmma::store_matrix_sync(pw, acc[i][j], 20, wmma::mem_row_major);
                __syncwarp();
                float4 a = *reinterpret_cast<const float4*>(&pw[pr * 20 + pc]);
                float4 b = *reinterpret_cast<const float4*>(&pw[pr * 20 + pc + 4]);
                union { uint4 u; __half2 h[4]; } pk;
                pk.h[0] = __floats2half2_rn(a.x, a.y);
                pk.h[1] = __floats2half2_rn(a.z, a.w);
                pk.h[2] = __floats2half2_rn(b.x, b.y);
                pk.h[3] = __floats2half2_rn(b.z, b.w);
                *reinterpret_cast<uint4*>(
                    &Out[(rbase + pr) * D_ + tn * P_BN + wc * 32 + j * 16 + pc]) = pk.u;
                __syncwarp();
            }
        }
    }
}

// ============================================================================
// Fused attention kernel. grid = (11, 8, 8), 256 threads.
// Temporal S/P use the block-diagonal-compressed 64x80 layout:
//   cols 0..15  = diagonal tt tile (row-tile-local K rows)
//   cols 16..79 = others (Kts/Vts) tiles
// S-MMA 128->80 tiles/iter, PV-MMA 128->80 tiles/iter; bit-identical math.
// ============================================================================
constexpr int ST  = 72;
constexpr int SPD = 84;    // floats stride for S (80 + pad)
constexpr int PHD = 88;    // halves stride for P (80 + pad)
constexpr int SMEM_ATT =
    64 * ST * 2 + 128 * ST * 2 + 128 * ST * 2
  + 64 * SPD * 4 + 64 * PHD * 2 + 3 * 64 * 4;

__device__ __forceinline__ void temporal_attn_body(
    char* smc, const float* bq, const float* bk, const float* bv, float* out)
{
    __half* Ql  = reinterpret_cast<__half*>(smc);
    __half* Kst = Ql  + 64 * ST;
    __half* Vst = Kst + 128 * ST;
    float*  SP  = reinterpret_cast<float*>(Vst + 128 * ST);
    __half* Ph  = reinterpret_cast<__half*>(SP + 64 * SPD);
    float*  bqs = reinterpret_cast<float*>(Ph + 64 * PHD);
    float*  bks = bqs + 64;
    float*  bvs = bks + 64;

    const int tid  = threadIdx.x;
    const int warp = tid >> 5;
    const int lane = tid & 31;
    const int b  = blockIdx.z, h = blockIdx.y;
    const int l0 = blockIdx.x * 64;
    const int cb = h * DH_;
    const int c4 = (tid & 15) * 4;

    if (tid < 64) {
        bqs[tid] = bq[cb + tid];
        bks[tid] = bk[cb + tid];
        bvs[tid] = bv[cb + tid];
    }
    // zero P diag region (cols 0..15) once; each iter rewrites only its 8 diag
    // entries per row, the other 8 stay zero forever.
    for (int idx = tid; idx < 64 * 8; idx += 256) {
        int r = idx >> 3, c = (idx & 7) * 2;
        *reinterpret_cast<__half2*>(&Ph[r * PHD + c]) = __floats2half2_rn(0.f, 0.f);
    }
    __syncthreads();

    const __half2 bq01 = __floats2half2_rn(bqs[c4],     bqs[c4 + 1]);
    const __half2 bq23 = __floats2half2_rn(bqs[c4 + 2], bqs[c4 + 3]);
    const __half2 bk01 = __floats2half2_rn(bks[c4],     bks[c4 + 1]);
    const __half2 bk23 = __floats2half2_rn(bks[c4 + 2], bks[c4 + 3]);
    const __half2 bv01 = __floats2half2_rn(bvs[c4],     bvs[c4 + 1]);
    const __half2 bv23 = __floats2half2_rn(bvs[c4 + 2], bvs[c4 + 3]);

#pragma unroll
    for (int i = 0; i < 4; i++) {
        int idx = tid + i * 256;
        int o = idx >> 4;
        size_t srow = (size_t)(b * SS_ + 8 + o) * D_ + cb + c4;
        uint2 kr = *reinterpret_cast<const uint2*>(&g_ss[1][srow]);
        *reinterpret_cast<__half2*>(&Kst[(64 + o) * ST + c4])     = __hadd2(*reinterpret_cast<__half2*>(&kr.x), bk01);
        *reinterpret_cast<__half2*>(&Kst[(64 + o) * ST + c4 + 2]) = __hadd2(*reinterpret_cast<__half2*>(&kr.y), bk23);
        uint2 vr = *reinterpret_cast<const uint2*>(&g_ss[2][srow]);
        *reinterpret_cast<__half2*>(&Vst[(64 + o) * ST + c4])     = __hadd2(*reinterpret_cast<__half2*>(&vr.x), bv01);
        *reinterpret_cast<__half2*>(&Vst[(64 + o) * ST + c4 + 2]) = __hadd2(*reinterpret_cast<__half2*>(&vr.y), bv23);
    }

    // ---- register prefetch of iteration 0's Q/K/V ----
    uint2 pq[4], pk_[4], pv[4];
    auto prefetch = [&](int li0) {
        const size_t rbase = (size_t)b * 4096 + (size_t)(l0 + li0) * 8;
#pragma unroll
        for (int i = 0; i < 4; i++) {
            int idx = tid + i * 256;
            int r = idx >> 4;
            size_t off = (rbase + r) * D_ + cb + c4;
            pq[i]  = *reinterpret_cast<const uint2*>(&g_tt[0][off]);
            pk_[i] = *reinterpret_cast<const uint2*>(&g_tt[1][off]);
            pv[i]  = *reinterpret_cast<const uint2*>(&g_tt[2][off]);
        }
    };
    prefetch(0);
    __syncthreads();

    for (int li0 = 0; li0 < 64; li0 += 8) {
        // ---- stage from prefetch registers ----
#pragma unroll
        for (int i = 0; i < 4; i++) {
            int idx = tid + i * 256;
            int r = idx >> 4;
            *reinterpret_cast<__half2*>(&Ql[r * ST + c4])     = __hadd2(*reinterpret_cast<__half2*>(&pq[i].x), bq01);
            *reinterpret_cast<__half2*>(&Ql[r * ST + c4 + 2]) = __hadd2(*reinterpret_cast<__half2*>(&pq[i].y), bq23);
            *reinterpret_cast<__half2*>(&Kst[r * ST + c4])     = __hadd2(*reinterpret_cast<__half2*>(&pk_[i].x), bk01);
            *reinterpret_cast<__half2*>(&Kst[r * ST + c4 + 2]) = __hadd2(*reinterpret_cast<__half2*>(&pk_[i].y), bk23);
            *reinterpret_cast<__half2*>(&Vst[r * ST + c4])     = __hadd2(*reinterpret_cast<__half2*>(&pv[i].x), bv01);
            *reinterpret_cast<__half2*>(&Vst[r * ST + c4 + 2]) = __hadd2(*reinterpret_cast<__half2*>(&pv[i].y), bv23);
        }
        __syncthreads();

        if (li0 + 8 < 64) prefetch(li0 + 8);

        // ---- S (64x80): diag tt tile + 4 ot tiles per row-tile ----
        {
            const int rt = warp >> 1;
            const int half = warp & 1;
            wmma::fragment<wmma::matrix_a, 16, 16, 16, __half, wmma::row_major> af;
            if (half == 0) {
                // col tiles 0 (diag: Kl rows rt*16), 1, 2 (Kts rows 0,16)
                wmma::fragment<wmma::accumulator, 16, 16, 16, float> sacc[3];
#pragma unroll
                for (int j = 0; j < 3; j++) wmma::fill_fragment(sacc[j], 0.0f);
#pragma unroll
                for (int ks = 0; ks < 4; ks++) {
                    wmma::load_matrix_sync(af, &Ql[(rt * 16) * ST + ks * 16], ST);
                    wmma::fragment<wmma::matrix_b, 16, 16, 16, __half, wmma::col_major> bf;
                    wmma::load_matrix_sync(bf, &Kst[(rt * 16) * ST + ks * 16], ST);
                    wmma::mma_sync(sacc[0], af, bf, sacc[0]);
                    wmma::load_matrix_sync(bf, &Kst[64 * ST + ks * 16], ST);
                    wmma::mma_sync(sacc[1], af, bf, sacc[1]);
                    wmma::load_matrix_sync(bf, &Kst[80 * ST + ks * 16], ST);
                    wmma::mma_sync(sacc[2], af, bf, sacc[2]);
                }
#pragma unroll
                for (int j = 0; j < 3; j++)
                    wmma::store_matrix_sync(&SP[(rt * 16) * SPD + j * 16], sacc[j],
                                            SPD, wmma::mem_row_major);
            } else {
                // col tiles 3, 4 (Kts rows 32, 48)
                wmma::fragment<wmma::accumulator, 16, 16, 16, float> sacc[2];
#pragma unroll
                for (int j = 0; j < 2; j++) wmma::fill_fragment(sacc[j], 0.0f);
#pragma unroll
                for (int ks = 0; ks < 4; ks++) {
                    wmma::load_matrix_sync(af, &Ql[(rt * 16) * ST + ks * 16], ST);
                    wmma::fragment<wmma::matrix_b, 16, 16, 16, __half, wmma::col_major> bf;
                    wmma::load_matrix_sync(bf, &Kst[96 * ST + ks * 16], ST);
                    wmma::mma_sync(sacc[0], af, bf, sacc[0]);
                    wmma::load_matrix_sync(bf, &Kst[112 * ST + ks * 16], ST);
                    wmma::mma_sync(sacc[1], af, bf, sacc[1]);
                }
#pragma unroll
                for (int j = 0; j < 2; j++)
                    wmma::store_matrix_sync(&SP[(rt * 16) * SPD + (3 + j) * 16], sacc[j],
                                            SPD, wmma::mem_row_major);
            }
        }
        __syncthreads();

        // ---- softmax (warp -> 8 rows; diag at cols 0..15, ot at 16..79) ----
        for (int i = 0; i < 8; i++) {
            int r = warp * 8 + i;
            int li = r >> 3;
            int dcol = (li & 1) * 8;
            float* Sr = &SP[r * SPD];
            __half* Pr = &Ph[r * PHD];
            float v0 = Sr[16 + lane] * 0.125f;
            float v1 = Sr[48 + lane] * 0.125f;
            float vs = (lane < 8) ? Sr[dcol + lane] * 0.125f : -3.4e38f;
            float mx = fmaxf(fmaxf(v0, v1), vs);
#pragma unroll
            for (int s = 16; s; s >>= 1) mx = fmaxf(mx, __shfl_xor_sync(0xffffffffu, mx, s));
            float e0 = __expf(v0 - mx), e1 = __expf(v1 - mx);
            float es = (lane < 8) ? __expf(vs - mx) : 0.f;
            float smv = e0 + e1 + es;
#pragma unroll
            for (int s = 16; s; s >>= 1) smv += __shfl_xor_sync(0xffffffffu, smv, s);
            float inv = 1.0f / smv;
            float p0 = e0 * inv, p1 = e1 * inv;
            size_t abase = OFF_TATT + ((size_t)(b * 8 + h) * 4096 + (size_t)(l0 + li0 + li) * 8 + (r & 7)) * 72;
            __stcs(&out[abase + 8 + lane],  p0);
            __stcs(&out[abase + 40 + lane], p1);
            float ps = es * inv;
            if (lane < 8) __stcs(&out[abase + lane], ps);
            Pr[16 + lane] = __float2half_rn(p0);
            Pr[48 + lane] = __float2half_rn(p1);
            if (lane < 8) Pr[dcol + lane] = __float2half_rn(ps);
        }
        __syncthreads();

        // ---- Out = P(64x80) . [Vl-rowtile; Vts] (5 k-steps) ----
        {
            const int rt = warp >> 1;
            const int ct0 = (warp & 1) * 2;
            wmma::fragment<wmma::accumulator, 16, 16, 16, float> oacc[2];
#pragma unroll
            for (int j = 0; j < 2; j++) wmma::fill_fragment(oacc[j], 0.0f);
#pragma unroll
            for (int ks = 0; ks < 5; ks++) {
                wmma::fragment<wmma::matrix_a, 16, 16, 16, __half, wmma::row_major> af;
                wmma::load_matrix_sync(af, &Ph[(rt * 16) * PHD + ks * 16], PHD);
                const int brow = (ks == 0) ? (rt * 16) : (64 + (ks - 1) * 16);
#pragma unroll
                for (int j = 0; j < 2; j++) {
                    wmma::fragment<wmma::matrix_b, 16, 16, 16, __half, wmma::row_major> bf;
                    wmma::load_matrix_sync(bf, &Vst[brow * ST + (ct0 + j) * 16], ST);
                    wmma::mma_sync(oacc[j], af, bf, oacc[j]);
                }
            }
            const size_t g0 = (size_t)(b * 4104 + 8 + (l0 + li0) * 8 + rt * 16);
#pragma unroll
            for (int j = 0; j < 2; j++)
                wmma::store_matrix_sync(out + g0 * D_ + cb + (ct0 + j) * 16, oacc[j],
                                        D_, wmma::mem_row_major);
        }
        __syncthreads();
    }
}

__device__ __forceinline__ void others_attn_body(
    char* smc, const float* bq, const float* bk, const float* bv, float* out)
{
    float* Qc  = reinterpret_cast<float*>(smc);
    float* KV  = Qc + 24 * 65;
    float* S   = KV + 72 * 65;
    float* bq_s = S + 24 * 73;
    float* bk_s = bq_s + 64;
    float* bv_s = bk_s + 64;

    const int tid = threadIdx.x;
    const int m0 = (blockIdx.x - 8) * 24;
    const int h = blockIdx.y, b = blockIdx.z;
    const int cb = h * DH_;

    if (tid < 64) {
        bq_s[tid] = bq[cb + tid];
        bk_s[tid] = bk[cb + tid];
        bv_s[tid] = bv[cb + tid];
    }
    __syncthreads();

    for (int idx = tid; idx < 72 * 64; idx += 256) {
        int n = idx >> 6, d = idx & 63;
        KV[n * 65 + d] = __half2float(g_ss[1][(size_t)(b * SS_ + n) * D_ + cb + d]) + bk_s[d];
    }
    for (int idx = tid; idx < 24 * 64; idx += 256) {
        int i = idx >> 6, d = idx & 63;
        Qc[i * 65 + d] = __half2float(g_ss[0][(size_t)(b * SS_ + m0 + i) * D_ + cb + d]) + bq_s[d];
    }
    __syncthreads();

    for (int e = tid; e < 24 * 72; e += 256) {
        int i = e / 72, n = e - i * 72;
        float acc = 0.f;
#pragma unroll
        for (int d = 0; d < 64; d++) acc = fmaf(Qc[i * 65 + d], KV[n * 65 + d], acc);
        S[i * 73 + n] = acc * 0.125f;
    }
    __syncthreads();

    {
        int w = tid >> 5, lane = tid & 31;
        for (int i = w; i < 24; i += 8) {
            float v0 = S[i * 73 + lane];
            float v1 = S[i * 73 + lane + 32];
            float v2 = (lane < 8) ? S[i * 73 + lane + 64] : -3.4e38f;
            float mx = fmaxf(fmaxf(v0, v1), v2);
#pragma unroll
            for (int s = 16; s; s >>= 1) mx = fmaxf(mx, __shfl_xor_sync(0xffffffffu, mx, s));
            float e0 = __expf(v0 - mx), e1 = __expf(v1 - mx);
            float e2 = (lane < 8) ? __expf(v2 - mx) : 0.f;
            float smv = e0 + e1 + e2;
#pragma unroll
            for (int s = 16; s; s >>= 1) smv += __shfl_xor_sync(0xffffffffu, smv, s);
            float inv = 1.0f / smv;
            size_t abase = OFF_OATT + ((size_t)(b * 8 + h) * 72 + (m0 + i)) * 72;
            float p0 = e0 * inv, p1 = e1 * inv;
            S[i * 73 + lane] = p0;       __stcs(&out[abase + lane],      p0);
            S[i * 73 + lane + 32] = p1;  __stcs(&out[abase + lane + 32], p1);
            if (lane < 8) {
                float p2 = e2 * inv;
                S[i * 73 + lane + 64] = p2;
                __stcs(&out[abase + lane + 64], p2);
            }
        }
    }
    __syncthreads();

    for (int idx = tid; idx < 72 * 64; idx += 256) {
        int n = idx >> 6, d = idx & 63;
        KV[n * 65 + d] = __half2float(g_ss[2][(size_t)(b * SS_ + n) * D_ + cb + d]) + bv_s[d];
    }
    __syncthreads();

    for (int e = tid; e < 24 * 64; e += 256) {
        int i = e >> 6, d = e & 63;
        float acc = 0.f;
#pragma unroll
        for (int n = 0; n < 72; n++) acc = fmaf(S[i * 73 + n], KV[n * 65 + d], acc);
        int ng = m0 + i;
        int p = h * 4608 + ng * 64 + d;
        int j = p >> 9;
        int c = p & 511;
        if (j < 8)
            out[(size_t)(b * 4104 + j) * D_ + c] = acc;
        else
            out[OFF_OOUT + (size_t)(b * 64 + (j - 8)) * D_ + c] = acc;
    }
}

__global__ __launch_bounds__(256) void attn_fused_kernel(
    const float* __restrict__ bq, const float* __restrict__ bk,
    const float* __restrict__ bv, float* __restrict__ out)
{
    extern __shared__ char smc[];
    if (blockIdx.x < 8)
        temporal_attn_body(smc, bq, bk, bv, out);
    else
        others_attn_body(smc, bq, bk, bv, out);
}

// ============================================================================
extern "C" void kernel_launch(void* const* d_in, const int* in_sizes, int n_in,
                              void* d_out, int out_size)
{
    const float* Xt = (const float*)d_in[0];
    const float* Xo = (const float*)d_in[1];
    const float* Wq = (const float*)d_in[2];
    const float* bq = (const float*)d_in[3];
    const float* Wk = (const float*)d_in[4];
    const float* bk = (const float*)d_in[5];
    const float* Wv = (const float*)d_in[6];
    const float* bv = (const float*)d_in[7];
    float* out = (float*)d_out;

    cudaFuncSetAttribute((const void*)proj_gemm_all, cudaFuncAttributeMaxDynamicSharedMemorySize, SMEM_PROJ);
    cudaFuncSetAttribute((const void*)attn_fused_kernel, cudaFuncAttributeMaxDynamicSharedMemorySize, SMEM_ATT);

    convert_kernel<<<(NCONV + 255) / 256, 256>>>(Xt, Xo, Wq, Wk, Wv);
    proj_gemm_all<<<dim3(NTILE_M, D_ / P_BN, 3), 256, SMEM_PROJ>>>();
    attn_fused_kernel<<<dim3(11, 8, 8), 256, SMEM_ATT>>>(bq, bk, bv, out);
}